// round 1
// baseline (speedup 1.0000x reference)
#include <cuda_runtime.h>
#include <math.h>
#include <stdint.h>

// ---------------------------------------------------------------------------
// Problem constants (B = 1)
// ---------------------------------------------------------------------------
#define LTOK 4096
#define DMODEL 3072
#define NHEAD 24
#define HDIM 128
#define MLPD 12288
#define N1 (3 * DMODEL + MLPD)   // 21504 : w1 output width
#define K2 (DMODEL + MLPD)       // 15360 : w2 input width
#define EPSV 1e-6f
#define SM_SCALE 0.08838834764831843f  // HD^-0.5

// ---------------------------------------------------------------------------
// Scratch (static device globals -- no allocation allowed)
// ---------------------------------------------------------------------------
__device__ float g_sv[DMODEL];                 // silu(vec)
__device__ float g_m[3 * DMODEL];              // shift | scale | gate
__device__ float g_xmod[LTOK * DMODEL];        // modulated layernorm output
__device__ float g_h[LTOK * N1];               // GEMM1 output (qkv | mlp)
__device__ float g_q[NHEAD * LTOK * HDIM];     // q post norm+rope, head-major
__device__ float g_k[NHEAD * LTOK * HDIM];
__device__ float g_v[NHEAD * LTOK * HDIM];
__device__ float g_cat[LTOK * K2];             // [attn | gelu(mlp)]

// ---------------------------------------------------------------------------
// silu(vec)
// ---------------------------------------------------------------------------
__global__ void silu_k(const float* __restrict__ vec) {
    int i = blockIdx.x * blockDim.x + threadIdx.x;
    if (i < DMODEL) {
        float v = vec[i];
        g_sv[i] = v / (1.0f + expf(-v));
    }
}

// ---------------------------------------------------------------------------
// m = silu(vec) @ mod_w^T + mod_b   (one warp per output)
// ---------------------------------------------------------------------------
__global__ void mod_gemv(const float* __restrict__ mw, const float* __restrict__ mb) {
    int j = blockIdx.x * 8 + (threadIdx.x >> 5);
    int lane = threadIdx.x & 31;
    const float* wr = mw + (size_t)j * DMODEL;
    float s = 0.f;
    for (int k = lane; k < DMODEL; k += 32) s += g_sv[k] * wr[k];
#pragma unroll
    for (int o = 16; o; o >>= 1) s += __shfl_down_sync(0xffffffffu, s, o);
    if (lane == 0) g_m[j] = s + mb[j];
}

// ---------------------------------------------------------------------------
// x_mod = (1+scale)*layer_norm(x) + shift    (one block per token row)
// ---------------------------------------------------------------------------
__device__ __forceinline__ float block_sum256(float v, float* buf) {
#pragma unroll
    for (int o = 16; o; o >>= 1) v += __shfl_down_sync(0xffffffffu, v, o);
    int w = threadIdx.x >> 5;
    if ((threadIdx.x & 31) == 0) buf[w] = v;
    __syncthreads();
    float s = 0.f;
#pragma unroll
    for (int i = 0; i < 8; i++) s += buf[i];
    return s;
}

__global__ void __launch_bounds__(256) ln_mod(const float* __restrict__ x) {
    __shared__ float xs[DMODEL];
    __shared__ float rbuf[8];
    int row = blockIdx.x;
    const float* xr = x + (size_t)row * DMODEL;

    float s = 0.f;
    for (int i = threadIdx.x; i < DMODEL; i += 256) {
        float v = xr[i];
        xs[i] = v;
        s += v;
    }
    float mu = block_sum256(s, rbuf) * (1.0f / DMODEL);
    __syncthreads();
    float s2 = 0.f;
    for (int i = threadIdx.x; i < DMODEL; i += 256) {
        float d = xs[i] - mu;
        s2 += d * d;
    }
    float var = block_sum256(s2, rbuf) * (1.0f / DMODEL);
    float rstd = rsqrtf(var + EPSV);

    float* xm = g_xmod + (size_t)row * DMODEL;
    for (int i = threadIdx.x; i < DMODEL; i += 256) {
        float n = (xs[i] - mu) * rstd;
        xm[i] = (1.0f + g_m[DMODEL + i]) * n + g_m[i];
    }
}

// ---------------------------------------------------------------------------
// SGEMM (NT): C[m,n] = sum_k A[m,k] * B[n,k] + bias[n]
// EPI==1: C = xres + gate[n] * (acc + bias[n])
// 128x128 block, BK=8, 256 threads, 8x8 micro-tiles. Dims must divide evenly.
// ---------------------------------------------------------------------------
template <int EPI>
__global__ void __launch_bounds__(256)
sgemm_nt(const float* __restrict__ A, const float* __restrict__ B,
         float* __restrict__ C, int N, int K,
         const float* __restrict__ bias,
         const float* __restrict__ xres, const float* __restrict__ gate) {
    __shared__ float As[8][128];
    __shared__ float Bs[8][128];
    const int bm = blockIdx.y * 128;
    const int bn = blockIdx.x * 128;
    const int tid = threadIdx.x;
    const int tx = tid & 15, ty = tid >> 4;
    const int lrow = tid >> 1;
    const int lk = (tid & 1) * 4;
    const float* Ag = A + (size_t)(bm + lrow) * K + lk;
    const float* Bg = B + (size_t)(bn + lrow) * K + lk;

    float acc[8][8] = {};
    for (int kt = 0; kt < K; kt += 8) {
        float4 av = *reinterpret_cast<const float4*>(Ag + kt);
        float4 bv = *reinterpret_cast<const float4*>(Bg + kt);
        As[lk + 0][lrow] = av.x; As[lk + 1][lrow] = av.y;
        As[lk + 2][lrow] = av.z; As[lk + 3][lrow] = av.w;
        Bs[lk + 0][lrow] = bv.x; Bs[lk + 1][lrow] = bv.y;
        Bs[lk + 2][lrow] = bv.z; Bs[lk + 3][lrow] = bv.w;
        __syncthreads();
#pragma unroll
        for (int k = 0; k < 8; k++) {
            float a[8], b[8];
            *(float4*)(a)     = *(const float4*)&As[k][ty * 8];
            *(float4*)(a + 4) = *(const float4*)&As[k][ty * 8 + 4];
            *(float4*)(b)     = *(const float4*)&Bs[k][tx * 8];
            *(float4*)(b + 4) = *(const float4*)&Bs[k][tx * 8 + 4];
#pragma unroll
            for (int i = 0; i < 8; i++)
#pragma unroll
                for (int j = 0; j < 8; j++)
                    acc[i][j] = fmaf(a[i], b[j], acc[i][j]);
        }
        __syncthreads();
    }
#pragma unroll
    for (int i = 0; i < 8; i++) {
        const int row = bm + ty * 8 + i;
#pragma unroll
        for (int j = 0; j < 8; j++) {
            const int col = bn + tx * 8 + j;
            float v = acc[i][j] + bias[col];
            if (EPI == 1) v = xres[(size_t)row * N + col] + gate[col] * v;
            C[(size_t)row * N + col] = v;
        }
    }
}

// ---------------------------------------------------------------------------
// QKV prep: RMSNorm(q,k) + RoPE (via pe table) + head-major relayout.
// grid (LTOK, NHEAD), 128 threads (one per headdim element).
// ---------------------------------------------------------------------------
__global__ void __launch_bounds__(128)
qkv_prep(const float* __restrict__ pe,
         const float* __restrict__ q_scale, const float* __restrict__ k_scale) {
    int i = blockIdx.x;       // token
    int hh = blockIdx.y;      // head
    int d = threadIdx.x;      // 0..127

    const float* hp = g_h + (size_t)i * N1 + hh * HDIM;
    float qv = hp[d];
    float kv = hp[DMODEL + d];
    float vv = hp[2 * DMODEL + d];

    // block (128-thread) sum of squares for q and k
    __shared__ float rb[2][4];
    float sq = qv * qv, sk = kv * kv;
#pragma unroll
    for (int o = 16; o; o >>= 1) {
        sq += __shfl_down_sync(0xffffffffu, sq, o);
        sk += __shfl_down_sync(0xffffffffu, sk, o);
    }
    if ((d & 31) == 0) { rb[0][d >> 5] = sq; rb[1][d >> 5] = sk; }
    __syncthreads();
    float ssq = rb[0][0] + rb[0][1] + rb[0][2] + rb[0][3];
    float ssk = rb[1][0] + rb[1][1] + rb[1][2] + rb[1][3];
    float rq = rsqrtf(ssq * (1.0f / HDIM) + EPSV);
    float rk = rsqrtf(ssk * (1.0f / HDIM) + EPSV);

    float qn = qv * rq * q_scale[d];
    float kn = kv * rk * k_scale[d];

    // rope: pe layout (L, HD/2, 2, 2): [c, -s; s, c]
    int e = d >> 1;
    int base = (i * (HDIM / 2) + e) * 4 + (d & 1) * 2;
    float p0 = pe[base], p1 = pe[base + 1];
    float qp = __shfl_xor_sync(0xffffffffu, qn, 1);
    float kp = __shfl_xor_sync(0xffffffffu, kn, 1);
    float qe = (d & 1) ? qp : qn, qo = (d & 1) ? qn : qp;
    float ke = (d & 1) ? kp : kn, ko = (d & 1) ? kn : kp;
    float qr = p0 * qe + p1 * qo;
    float kr = p0 * ke + p1 * ko;

    size_t o = ((size_t)hh * LTOK + i) * HDIM + d;
    g_q[o] = qr;
    g_k[o] = kr;
    g_v[o] = vv;
}

// ---------------------------------------------------------------------------
// Flash attention fp32: 64 queries x 64 keys per iteration, HD=128.
// grid (LTOK/64, NHEAD), 256 threads. Output written into g_cat[:, :3072].
// ---------------------------------------------------------------------------
#define FLASH_SMEM ((64 * 129 * 2 + 64 * 128 + 64 * 68 + 64 * 3 + 64 * 16) * 4)

__global__ void __launch_bounds__(256) flash_k() {
    extern __shared__ float sm[];
    float* Qs  = sm;                 // [64][129]
    float* Ks  = Qs + 64 * 129;      // [64][129]
    float* Vs  = Ks + 64 * 129;      // [64][128]
    float* Ps  = Vs + 64 * 128;      // [64][68]
    float* m_s = Ps + 64 * 68;       // [64]
    float* l_s = m_s + 64;           // [64]
    float* a_s = l_s + 64;           // [64]
    float* red = a_s + 64;           // [64][16]

    const int h = blockIdx.y;
    const int qb = blockIdx.x * 64;
    const int tid = threadIdx.x;
    const int tx = tid & 15, ty = tid >> 4;

    const float* Qg = g_q + ((size_t)h * LTOK + qb) * HDIM;
    const float* Kg = g_k + (size_t)h * LTOK * HDIM;
    const float* Vg = g_v + (size_t)h * LTOK * HDIM;

    // load + pre-scale Q (coalesced gmem, conflict-free scalar smem stores)
#pragma unroll
    for (int i = 0; i < 8; i++) {
        int lin = i * 256 + tid;           // float4 chunk id 0..2047
        int r = lin >> 5, c = (lin & 31) * 4;
        float4 v = *(const float4*)(Qg + r * HDIM + c);
        float* q = Qs + r * 129 + c;
        q[0] = v.x * SM_SCALE; q[1] = v.y * SM_SCALE;
        q[2] = v.z * SM_SCALE; q[3] = v.w * SM_SCALE;
    }
    if (tid < 64) { m_s[tid] = -1e30f; l_s[tid] = 0.f; }

    float o[4][8] = {};

    for (int kt = 0; kt < LTOK; kt += 64) {
        __syncthreads();  // previous tile's consumers done with Ks/Vs
#pragma unroll
        for (int i = 0; i < 8; i++) {
            int lin = i * 256 + tid;
            int r = lin >> 5, c = (lin & 31) * 4;
            float4 kv4 = *(const float4*)(Kg + (size_t)(kt + r) * HDIM + c);
            float* kp = Ks + r * 129 + c;
            kp[0] = kv4.x; kp[1] = kv4.y; kp[2] = kv4.z; kp[3] = kv4.w;
            float4 vv4 = *(const float4*)(Vg + (size_t)(kt + r) * HDIM + c);
            *(float4*)(Vs + r * HDIM + c) = vv4;
        }
        __syncthreads();

        // S = Q K^T (4x4 frag per thread)
        float s[4][4] = {};
#pragma unroll 8
        for (int k = 0; k < HDIM; k++) {
            float a0 = Qs[(ty * 4 + 0) * 129 + k];
            float a1 = Qs[(ty * 4 + 1) * 129 + k];
            float a2 = Qs[(ty * 4 + 2) * 129 + k];
            float a3 = Qs[(ty * 4 + 3) * 129 + k];
            float b0 = Ks[(tx * 4 + 0) * 129 + k];
            float b1 = Ks[(tx * 4 + 1) * 129 + k];
            float b2 = Ks[(tx * 4 + 2) * 129 + k];
            float b3 = Ks[(tx * 4 + 3) * 129 + k];
            s[0][0] = fmaf(a0, b0, s[0][0]); s[0][1] = fmaf(a0, b1, s[0][1]);
            s[0][2] = fmaf(a0, b2, s[0][2]); s[0][3] = fmaf(a0, b3, s[0][3]);
            s[1][0] = fmaf(a1, b0, s[1][0]); s[1][1] = fmaf(a1, b1, s[1][1]);
            s[1][2] = fmaf(a1, b2, s[1][2]); s[1][3] = fmaf(a1, b3, s[1][3]);
            s[2][0] = fmaf(a2, b0, s[2][0]); s[2][1] = fmaf(a2, b1, s[2][1]);
            s[2][2] = fmaf(a2, b2, s[2][2]); s[2][3] = fmaf(a2, b3, s[2][3]);
            s[3][0] = fmaf(a3, b0, s[3][0]); s[3][1] = fmaf(a3, b1, s[3][1]);
            s[3][2] = fmaf(a3, b2, s[3][2]); s[3][3] = fmaf(a3, b3, s[3][3]);
        }

        // row-max reduce
#pragma unroll
        for (int r = 0; r < 4; r++) {
            float m0 = fmaxf(fmaxf(s[r][0], s[r][1]), fmaxf(s[r][2], s[r][3]));
            red[(ty * 4 + r) * 16 + tx] = m0;
        }
        __syncthreads();
        if (tid < 64) {
            float rm = -1e30f;
#pragma unroll
            for (int t = 0; t < 16; t++) rm = fmaxf(rm, red[tid * 16 + t]);
            float mo = m_s[tid];
            float mn = fmaxf(mo, rm);
            a_s[tid] = __expf(mo - mn);
            m_s[tid] = mn;
        }
        __syncthreads();

        // P = exp(S - m), partial sums, rescale O
#pragma unroll
        for (int r = 0; r < 4; r++) {
            float mn = m_s[ty * 4 + r];
            float al = a_s[ty * 4 + r];
            float rs = 0.f;
#pragma unroll
            for (int c = 0; c < 4; c++) {
                float p = __expf(s[r][c] - mn);
                Ps[(ty * 4 + r) * 68 + tx * 4 + c] = p;
                rs += p;
            }
            red[(ty * 4 + r) * 16 + tx] = rs;
#pragma unroll
            for (int c = 0; c < 8; c++) o[r][c] *= al;
        }
        __syncthreads();
        if (tid < 64) {
            float rs = 0.f;
#pragma unroll
            for (int t = 0; t < 16; t++) rs += red[tid * 16 + t];
            l_s[tid] = l_s[tid] * a_s[tid] + rs;
        }

        // O += P @ V
#pragma unroll 4
        for (int n = 0; n < 64; n++) {
            float4 v0 = *(const float4*)(Vs + n * HDIM + tx * 8);
            float4 v1 = *(const float4*)(Vs + n * HDIM + tx * 8 + 4);
            float vv[8] = {v0.x, v0.y, v0.z, v0.w, v1.x, v1.y, v1.z, v1.w};
#pragma unroll
            for (int r = 0; r < 4; r++) {
                float p = Ps[(ty * 4 + r) * 68 + n];
#pragma unroll
                for (int c = 0; c < 8; c++) o[r][c] = fmaf(p, vv[c], o[r][c]);
            }
        }
    }
    __syncthreads();

    // finalize: divide by l, write into concat buffer columns [h*128, h*128+128)
#pragma unroll
    for (int r = 0; r < 4; r++) {
        float inv = 1.0f / l_s[ty * 4 + r];
        int row = qb + ty * 4 + r;
        float* op = g_cat + (size_t)row * K2 + h * HDIM + tx * 8;
#pragma unroll
        for (int c = 0; c < 8; c++) op[c] = o[r][c] * inv;
    }
}

// ---------------------------------------------------------------------------
// gelu(mlp) into concat buffer columns [3072, 15360)
// ---------------------------------------------------------------------------
__device__ __forceinline__ float gelu_t(float x) {
    return 0.5f * x * (1.0f + tanhf(0.7978845608028654f * (x + 0.044715f * x * x * x)));
}

__global__ void __launch_bounds__(256) gelu_cat() {
    int idx = blockIdx.x * 256 + threadIdx.x;          // float4 index over L*MLPD/4
    const int per_row = MLPD / 4;
    if (idx >= LTOK * per_row) return;
    int row = idx / per_row;
    int c4 = idx - row * per_row;
    float4 v = *(const float4*)(g_h + (size_t)row * N1 + 3 * DMODEL + c4 * 4);
    float4 r;
    r.x = gelu_t(v.x); r.y = gelu_t(v.y); r.z = gelu_t(v.z); r.w = gelu_t(v.w);
    *(float4*)(g_cat + (size_t)row * K2 + DMODEL + c4 * 4) = r;
}

// ---------------------------------------------------------------------------
// launch
// ---------------------------------------------------------------------------
extern "C" void kernel_launch(void* const* d_in, const int* in_sizes, int n_in,
                              void* d_out, int out_size) {
    const float* x   = (const float*)d_in[0];
    const float* vec = (const float*)d_in[1];
    const float* pe  = (const float*)d_in[2];
    const float* w1  = (const float*)d_in[3];
    const float* b1  = (const float*)d_in[4];
    const float* w2  = (const float*)d_in[5];
    const float* b2  = (const float*)d_in[6];
    const float* mw  = (const float*)d_in[7];
    const float* mb  = (const float*)d_in[8];
    const float* qsc = (const float*)d_in[9];
    const float* ksc = (const float*)d_in[10];
    float* out = (float*)d_out;

    float *p_xmod, *p_h, *p_cat, *p_m;
    cudaGetSymbolAddress((void**)&p_xmod, g_xmod);
    cudaGetSymbolAddress((void**)&p_h, g_h);
    cudaGetSymbolAddress((void**)&p_cat, g_cat);
    cudaGetSymbolAddress((void**)&p_m, g_m);

    cudaFuncSetAttribute(flash_k, cudaFuncAttributeMaxDynamicSharedMemorySize,
                         FLASH_SMEM);

    silu_k<<<(DMODEL + 255) / 256, 256>>>(vec);
    mod_gemv<<<(3 * DMODEL) / 8, 256>>>(mw, mb);
    ln_mod<<<LTOK, 256>>>(x);

    // h = x_mod @ w1^T + b1
    sgemm_nt<0><<<dim3(N1 / 128, LTOK / 128), 256>>>(
        p_xmod, w1, p_h, N1, DMODEL, b1, nullptr, nullptr);

    qkv_prep<<<dim3(LTOK, NHEAD), 128>>>(pe, qsc, ksc);

    flash_k<<<dim3(LTOK / 64, NHEAD), 256, FLASH_SMEM>>>();

    gelu_cat<<<(LTOK * (MLPD / 4)) / 256, 256>>>();

    // out = x + gate * (cat @ w2^T + b2)
    sgemm_nt<1><<<dim3(DMODEL / 128, LTOK / 128), 256>>>(
        p_cat, w2, out, DMODEL, K2, b2, x, p_m + 2 * DMODEL);
}

// round 3
// speedup vs baseline: 2.1582x; 2.1582x over previous
#include <cuda_runtime.h>
#include <math.h>
#include <stdint.h>

// ---------------------------------------------------------------------------
// Problem constants (B = 1)
// ---------------------------------------------------------------------------
#define LTOK 4096
#define DMODEL 3072
#define NHEAD 24
#define HDIM 128
#define MLPD 12288
#define N1 (3 * DMODEL + MLPD)   // 21504
#define K2 (DMODEL + MLPD)       // 15360
#define EPSV 1e-6f
#define SM_SCALE 0.08838834764831843f

// ---------------------------------------------------------------------------
// Scratch
// ---------------------------------------------------------------------------
__device__ float g_sv[DMODEL];
__device__ float g_m[3 * DMODEL];
__device__ float g_xmod[LTOK * DMODEL];
__device__ float g_h[LTOK * N1];
__device__ float g_q[NHEAD * LTOK * HDIM];
__device__ float g_k[NHEAD * LTOK * HDIM];
__device__ float g_v[NHEAD * LTOK * HDIM];
__device__ float g_cat[LTOK * K2];

// ---------------------------------------------------------------------------
// helpers (sm_80-era PTX only: cp.async + mma.sync -- safe for plain sm_103)
// ---------------------------------------------------------------------------
__device__ __forceinline__ uint32_t smem_u32(const void* p) {
    uint32_t a;
    asm("{ .reg .u64 t; cvta.to.shared.u64 t, %1; cvt.u32.u64 %0, t; }"
        : "=r"(a) : "l"(p));
    return a;
}
__device__ __forceinline__ void cp_async16(uint32_t s, const void* g) {
    asm volatile("cp.async.cg.shared.global [%0], [%1], 16;" :: "r"(s), "l"(g) : "memory");
}
__device__ __forceinline__ uint32_t tf32_bits(float x) {
    uint32_t r;
    asm("{ .reg .b32 t; cvt.rna.tf32.f32 t, %1; mov.b32 %0, t; }" : "=r"(r) : "f"(x));
    return r;
}
__device__ __forceinline__ void mma_tf32(float* c, const uint32_t* a, const uint32_t* b) {
    asm volatile(
        "mma.sync.aligned.m16n8k8.row.col.f32.tf32.tf32.f32 "
        "{%0,%1,%2,%3}, {%4,%5,%6,%7}, {%8,%9}, {%0,%1,%2,%3};"
        : "+f"(c[0]), "+f"(c[1]), "+f"(c[2]), "+f"(c[3])
        : "r"(a[0]), "r"(a[1]), "r"(a[2]), "r"(a[3]), "r"(b[0]), "r"(b[1]));
}

// ---------------------------------------------------------------------------
// small kernels
// ---------------------------------------------------------------------------
__global__ void silu_k(const float* __restrict__ vec) {
    int i = blockIdx.x * blockDim.x + threadIdx.x;
    if (i < DMODEL) {
        float v = vec[i];
        g_sv[i] = v / (1.0f + expf(-v));
    }
}

__global__ void mod_gemv(const float* __restrict__ mw, const float* __restrict__ mb) {
    int j = blockIdx.x * 8 + (threadIdx.x >> 5);
    int lane = threadIdx.x & 31;
    const float* wr = mw + (size_t)j * DMODEL;
    float s = 0.f;
    for (int k = lane; k < DMODEL; k += 32) s += g_sv[k] * wr[k];
#pragma unroll
    for (int o = 16; o; o >>= 1) s += __shfl_down_sync(0xffffffffu, s, o);
    if (lane == 0) g_m[j] = s + mb[j];
}

__device__ __forceinline__ float block_sum256(float v, float* buf) {
#pragma unroll
    for (int o = 16; o; o >>= 1) v += __shfl_down_sync(0xffffffffu, v, o);
    int w = threadIdx.x >> 5;
    if ((threadIdx.x & 31) == 0) buf[w] = v;
    __syncthreads();
    float s = 0.f;
#pragma unroll
    for (int i = 0; i < 8; i++) s += buf[i];
    return s;
}

__global__ void __launch_bounds__(256) ln_mod(const float* __restrict__ x) {
    __shared__ float xs[DMODEL];
    __shared__ float rbuf[8];
    int row = blockIdx.x;
    const float* xr = x + (size_t)row * DMODEL;
    float s = 0.f;
    for (int i = threadIdx.x; i < DMODEL; i += 256) {
        float v = xr[i];
        xs[i] = v;
        s += v;
    }
    float mu = block_sum256(s, rbuf) * (1.0f / DMODEL);
    __syncthreads();
    float s2 = 0.f;
    for (int i = threadIdx.x; i < DMODEL; i += 256) {
        float d = xs[i] - mu;
        s2 += d * d;
    }
    float var = block_sum256(s2, rbuf) * (1.0f / DMODEL);
    float rstd = rsqrtf(var + EPSV);
    float* xm = g_xmod + (size_t)row * DMODEL;
    for (int i = threadIdx.x; i < DMODEL; i += 256) {
        float n = (xs[i] - mu) * rstd;
        xm[i] = (1.0f + g_m[DMODEL + i]) * n + g_m[i];
    }
}

// ---------------------------------------------------------------------------
// tf32 mma.sync GEMM (NT): C[M,Nt] = A[M,K] @ B[Nt,K]^T (+bias, opt epilogue)
// 128x128 CTA tile, 8 warps (2x4), each warp 64x32. BK=16, 3-stage cp.async.
// tf32 rounding (cvt.rna) applied at fragment load.
// ---------------------------------------------------------------------------
#define BM 128
#define BN 128
#define BK 16
#define NSTG 3
#define SROW 20                          // 16 data floats + 4 pad (conflict-free)
#define TILE_FLOATS (BM * SROW)          // 2560 floats per operand tile
#define GEMM_SMEM (NSTG * 2 * TILE_FLOATS * 4)   // 61440 B

__device__ __forceinline__ void ld_stage(uint32_t As, uint32_t Bs,
                                         const float* __restrict__ Ag,
                                         const float* __restrict__ Bg,
                                         int K, int kb, int tid) {
#pragma unroll
    for (int it = 0; it < 2; ++it) {
        int id = it * 256 + tid;              // 512 float4 chunks per operand
        int row = id >> 2, c4 = id & 3;
        uint32_t off = (uint32_t)(row * SROW + c4 * 4) * 4u;
        const size_t goff = (size_t)row * K + kb + c4 * 4;
        cp_async16(As + off, Ag + goff);
        cp_async16(Bs + off, Bg + goff);
    }
}

template <int EPI>
__global__ void __launch_bounds__(256, 2)
mm_gemm(const float* __restrict__ A, const float* __restrict__ B,
        float* __restrict__ C, int Nt, int K,
        const float* __restrict__ bias,
        const float* __restrict__ xres, const float* __restrict__ gate) {
    extern __shared__ float smf[];
    const uint32_t sA = smem_u32(smf);
    const uint32_t sB = sA + NSTG * TILE_FLOATS * 4;

    const int tid = threadIdx.x;
    const int wid = tid >> 5, lane = tid & 31;
    const int gp = lane >> 2, qd = lane & 3;
    const int warpM = (wid >> 2) * 64;    // 2 warps over M
    const int warpN = (wid & 3) * 32;     // 4 warps over N
    const int bm = blockIdx.x * BM;
    const int bn = blockIdx.y * BN;

    const float* Ag = A + (size_t)bm * K;
    const float* Bg = B + (size_t)bn * K;
    const int nch = K / BK;

    float acc[4][4][4] = {};              // [mt][nt][reg]

    // prologue: stages 0, 1
    ld_stage(sA, sB, Ag, Bg, K, 0, tid);
    asm volatile("cp.async.commit_group;" ::: "memory");
    ld_stage(sA + TILE_FLOATS * 4, sB + TILE_FLOATS * 4, Ag, Bg, K, BK, tid);
    asm volatile("cp.async.commit_group;" ::: "memory");

    for (int j = 0; j < nch; ++j) {
        const int c = j + 2;
        if (c < nch) {
            const int st = c % NSTG;
            ld_stage(sA + st * TILE_FLOATS * 4, sB + st * TILE_FLOATS * 4,
                     Ag, Bg, K, c * BK, tid);
        }
        asm volatile("cp.async.commit_group;" ::: "memory");
        asm volatile("cp.async.wait_group 1;" ::: "memory");
        __syncthreads();

        const float* as = smf + (j % NSTG) * TILE_FLOATS;
        const float* bs = smf + NSTG * TILE_FLOATS + (j % NSTG) * TILE_FLOATS;
#pragma unroll
        for (int ks = 0; ks < 2; ++ks) {
            uint32_t af[4][4], bf[4][2];
#pragma unroll
            for (int mt = 0; mt < 4; ++mt) {
                const float* p = as + (warpM + mt * 16 + gp) * SROW + ks * 8 + qd;
                af[mt][0] = tf32_bits(p[0]);
                af[mt][1] = tf32_bits(p[8 * SROW]);
                af[mt][2] = tf32_bits(p[4]);
                af[mt][3] = tf32_bits(p[8 * SROW + 4]);
            }
#pragma unroll
            for (int nt = 0; nt < 4; ++nt) {
                const float* p = bs + (warpN + nt * 8 + gp) * SROW + ks * 8 + qd;
                bf[nt][0] = tf32_bits(p[0]);
                bf[nt][1] = tf32_bits(p[4]);
            }
#pragma unroll
            for (int mt = 0; mt < 4; ++mt)
#pragma unroll
                for (int nt = 0; nt < 4; ++nt)
                    mma_tf32(acc[mt][nt], af[mt], bf[nt]);
        }
        __syncthreads();
    }

    // epilogue: c0,c1 -> (row, col..col+1); c2,c3 -> (row+8, ...)
#pragma unroll
    for (int nt = 0; nt < 4; ++nt) {
        const int col = bn + warpN + nt * 8 + 2 * qd;
        const float b0 = bias[col], b1 = bias[col + 1];
        float g0 = 0.f, g1 = 0.f;
        if (EPI) { g0 = gate[col]; g1 = gate[col + 1]; }
#pragma unroll
        for (int mt = 0; mt < 4; ++mt) {
            const int r0 = bm + warpM + mt * 16 + gp;
#pragma unroll
            for (int half = 0; half < 2; ++half) {
                const int row = r0 + half * 8;
                float v0 = acc[mt][nt][half * 2 + 0] + b0;
                float v1 = acc[mt][nt][half * 2 + 1] + b1;
                const size_t off = (size_t)row * Nt + col;
                if (EPI) {
                    float2 xr = *(const float2*)(xres + off);
                    v0 = xr.x + g0 * v0;
                    v1 = xr.y + g1 * v1;
                }
                *(float2*)(C + off) = make_float2(v0, v1);
            }
        }
    }
}

// ---------------------------------------------------------------------------
// QKV prep: RMSNorm + RoPE + head-major relayout
// ---------------------------------------------------------------------------
__global__ void __launch_bounds__(128)
qkv_prep(const float* __restrict__ pe,
         const float* __restrict__ q_scale, const float* __restrict__ k_scale) {
    int i = blockIdx.x;
    int hh = blockIdx.y;
    int d = threadIdx.x;

    const float* hp = g_h + (size_t)i * N1 + hh * HDIM;
    float qv = hp[d];
    float kv = hp[DMODEL + d];
    float vv = hp[2 * DMODEL + d];

    __shared__ float rb[2][4];
    float sq = qv * qv, sk = kv * kv;
#pragma unroll
    for (int o = 16; o; o >>= 1) {
        sq += __shfl_down_sync(0xffffffffu, sq, o);
        sk += __shfl_down_sync(0xffffffffu, sk, o);
    }
    if ((d & 31) == 0) { rb[0][d >> 5] = sq; rb[1][d >> 5] = sk; }
    __syncthreads();
    float ssq = rb[0][0] + rb[0][1] + rb[0][2] + rb[0][3];
    float ssk = rb[1][0] + rb[1][1] + rb[1][2] + rb[1][3];
    float rq = rsqrtf(ssq * (1.0f / HDIM) + EPSV);
    float rk = rsqrtf(ssk * (1.0f / HDIM) + EPSV);

    float qn = qv * rq * q_scale[d];
    float kn = kv * rk * k_scale[d];

    int e = d >> 1;
    int base = (i * (HDIM / 2) + e) * 4 + (d & 1) * 2;
    float p0 = pe[base], p1 = pe[base + 1];
    float qp = __shfl_xor_sync(0xffffffffu, qn, 1);
    float kp = __shfl_xor_sync(0xffffffffu, kn, 1);
    float qe = (d & 1) ? qp : qn, qo = (d & 1) ? qn : qp;
    float ke = (d & 1) ? kp : kn, ko = (d & 1) ? kn : kp;
    float qr = p0 * qe + p1 * qo;
    float kr = p0 * ke + p1 * ko;

    size_t o = ((size_t)hh * LTOK + i) * HDIM + d;
    g_q[o] = qr;
    g_k[o] = kr;
    g_v[o] = vv;
}

// ---------------------------------------------------------------------------
// Flash attention fp32
// ---------------------------------------------------------------------------
#define FLASH_SMEM ((64 * 129 * 2 + 64 * 128 + 64 * 68 + 64 * 3 + 64 * 16) * 4)

__global__ void __launch_bounds__(256) flash_k() {
    extern __shared__ float sm[];
    float* Qs  = sm;
    float* Ks  = Qs + 64 * 129;
    float* Vs  = Ks + 64 * 129;
    float* Ps  = Vs + 64 * 128;
    float* m_s = Ps + 64 * 68;
    float* l_s = m_s + 64;
    float* a_s = l_s + 64;
    float* red = a_s + 64;

    const int h = blockIdx.y;
    const int qb = blockIdx.x * 64;
    const int tid = threadIdx.x;
    const int tx = tid & 15, ty = tid >> 4;

    const float* Qg = g_q + ((size_t)h * LTOK + qb) * HDIM;
    const float* Kg = g_k + (size_t)h * LTOK * HDIM;
    const float* Vg = g_v + (size_t)h * LTOK * HDIM;

#pragma unroll
    for (int i = 0; i < 8; i++) {
        int lin = i * 256 + tid;
        int r = lin >> 5, c = (lin & 31) * 4;
        float4 v = *(const float4*)(Qg + r * HDIM + c);
        float* q = Qs + r * 129 + c;
        q[0] = v.x * SM_SCALE; q[1] = v.y * SM_SCALE;
        q[2] = v.z * SM_SCALE; q[3] = v.w * SM_SCALE;
    }
    if (tid < 64) { m_s[tid] = -1e30f; l_s[tid] = 0.f; }

    float o[4][8] = {};

    for (int kt = 0; kt < LTOK; kt += 64) {
        __syncthreads();
#pragma unroll
        for (int i = 0; i < 8; i++) {
            int lin = i * 256 + tid;
            int r = lin >> 5, c = (lin & 31) * 4;
            float4 kv4 = *(const float4*)(Kg + (size_t)(kt + r) * HDIM + c);
            float* kp = Ks + r * 129 + c;
            kp[0] = kv4.x; kp[1] = kv4.y; kp[2] = kv4.z; kp[3] = kv4.w;
            float4 vv4 = *(const float4*)(Vg + (size_t)(kt + r) * HDIM + c);
            *(float4*)(Vs + r * HDIM + c) = vv4;
        }
        __syncthreads();

        float s[4][4] = {};
#pragma unroll 8
        for (int k = 0; k < HDIM; k++) {
            float a0 = Qs[(ty * 4 + 0) * 129 + k];
            float a1 = Qs[(ty * 4 + 1) * 129 + k];
            float a2 = Qs[(ty * 4 + 2) * 129 + k];
            float a3 = Qs[(ty * 4 + 3) * 129 + k];
            float b0 = Ks[(tx * 4 + 0) * 129 + k];
            float b1 = Ks[(tx * 4 + 1) * 129 + k];
            float b2 = Ks[(tx * 4 + 2) * 129 + k];
            float b3 = Ks[(tx * 4 + 3) * 129 + k];
            s[0][0] = fmaf(a0, b0, s[0][0]); s[0][1] = fmaf(a0, b1, s[0][1]);
            s[0][2] = fmaf(a0, b2, s[0][2]); s[0][3] = fmaf(a0, b3, s[0][3]);
            s[1][0] = fmaf(a1, b0, s[1][0]); s[1][1] = fmaf(a1, b1, s[1][1]);
            s[1][2] = fmaf(a1, b2, s[1][2]); s[1][3] = fmaf(a1, b3, s[1][3]);
            s[2][0] = fmaf(a2, b0, s[2][0]); s[2][1] = fmaf(a2, b1, s[2][1]);
            s[2][2] = fmaf(a2, b2, s[2][2]); s[2][3] = fmaf(a2, b3, s[2][3]);
            s[3][0] = fmaf(a3, b0, s[3][0]); s[3][1] = fmaf(a3, b1, s[3][1]);
            s[3][2] = fmaf(a3, b2, s[3][2]); s[3][3] = fmaf(a3, b3, s[3][3]);
        }

#pragma unroll
        for (int r = 0; r < 4; r++) {
            float m0 = fmaxf(fmaxf(s[r][0], s[r][1]), fmaxf(s[r][2], s[r][3]));
            red[(ty * 4 + r) * 16 + tx] = m0;
        }
        __syncthreads();
        if (tid < 64) {
            float rm = -1e30f;
#pragma unroll
            for (int t = 0; t < 16; t++) rm = fmaxf(rm, red[tid * 16 + t]);
            float mo = m_s[tid];
            float mn = fmaxf(mo, rm);
            a_s[tid] = __expf(mo - mn);
            m_s[tid] = mn;
        }
        __syncthreads();

#pragma unroll
        for (int r = 0; r < 4; r++) {
            float mn = m_s[ty * 4 + r];
            float al = a_s[ty * 4 + r];
            float rs = 0.f;
#pragma unroll
            for (int c = 0; c < 4; c++) {
                float p = __expf(s[r][c] - mn);
                Ps[(ty * 4 + r) * 68 + tx * 4 + c] = p;
                rs += p;
            }
            red[(ty * 4 + r) * 16 + tx] = rs;
#pragma unroll
            for (int c = 0; c < 8; c++) o[r][c] *= al;
        }
        __syncthreads();
        if (tid < 64) {
            float rs = 0.f;
#pragma unroll
            for (int t = 0; t < 16; t++) rs += red[tid * 16 + t];
            l_s[tid] = l_s[tid] * a_s[tid] + rs;
        }

#pragma unroll 4
        for (int n = 0; n < 64; n++) {
            float4 v0 = *(const float4*)(Vs + n * HDIM + tx * 8);
            float4 v1 = *(const float4*)(Vs + n * HDIM + tx * 8 + 4);
            float vv[8] = {v0.x, v0.y, v0.z, v0.w, v1.x, v1.y, v1.z, v1.w};
#pragma unroll
            for (int r = 0; r < 4; r++) {
                float p = Ps[(ty * 4 + r) * 68 + n];
#pragma unroll
                for (int c = 0; c < 8; c++) o[r][c] = fmaf(p, vv[c], o[r][c]);
            }
        }
    }
    __syncthreads();

#pragma unroll
    for (int r = 0; r < 4; r++) {
        float inv = 1.0f / l_s[ty * 4 + r];
        int row = qb + ty * 4 + r;
        float* op = g_cat + (size_t)row * K2 + h * HDIM + tx * 8;
#pragma unroll
        for (int c = 0; c < 8; c++) op[c] = o[r][c] * inv;
    }
}

// ---------------------------------------------------------------------------
// gelu(mlp) into concat buffer
// ---------------------------------------------------------------------------
__device__ __forceinline__ float gelu_t(float x) {
    return 0.5f * x * (1.0f + tanhf(0.7978845608028654f * (x + 0.044715f * x * x * x)));
}

__global__ void __launch_bounds__(256) gelu_cat() {
    int idx = blockIdx.x * 256 + threadIdx.x;
    const int per_row = MLPD / 4;
    if (idx >= LTOK * per_row) return;
    int row = idx / per_row;
    int c4 = idx - row * per_row;
    float4 v = *(const float4*)(g_h + (size_t)row * N1 + 3 * DMODEL + c4 * 4);
    float4 r;
    r.x = gelu_t(v.x); r.y = gelu_t(v.y);
    r.z = gelu_t(v.z); r.w = gelu_t(v.w);
    *(float4*)(g_cat + (size_t)row * K2 + DMODEL + c4 * 4) = r;
}

// ---------------------------------------------------------------------------
// launch
// ---------------------------------------------------------------------------
extern "C" void kernel_launch(void* const* d_in, const int* in_sizes, int n_in,
                              void* d_out, int out_size) {
    const float* x   = (const float*)d_in[0];
    const float* vec = (const float*)d_in[1];
    const float* pe  = (const float*)d_in[2];
    const float* w1  = (const float*)d_in[3];
    const float* b1  = (const float*)d_in[4];
    const float* w2  = (const float*)d_in[5];
    const float* b2  = (const float*)d_in[6];
    const float* mw  = (const float*)d_in[7];
    const float* mb  = (const float*)d_in[8];
    const float* qsc = (const float*)d_in[9];
    const float* ksc = (const float*)d_in[10];
    float* out = (float*)d_out;

    float *p_xmod, *p_h, *p_cat, *p_m;
    cudaGetSymbolAddress((void**)&p_xmod, g_xmod);
    cudaGetSymbolAddress((void**)&p_h, g_h);
    cudaGetSymbolAddress((void**)&p_cat, g_cat);
    cudaGetSymbolAddress((void**)&p_m, g_m);

    cudaFuncSetAttribute(flash_k, cudaFuncAttributeMaxDynamicSharedMemorySize, FLASH_SMEM);
    cudaFuncSetAttribute(mm_gemm<0>, cudaFuncAttributeMaxDynamicSharedMemorySize, GEMM_SMEM);
    cudaFuncSetAttribute(mm_gemm<1>, cudaFuncAttributeMaxDynamicSharedMemorySize, GEMM_SMEM);

    silu_k<<<(DMODEL + 255) / 256, 256>>>(vec);
    mod_gemv<<<(3 * DMODEL) / 8, 256>>>(mw, mb);
    ln_mod<<<LTOK, 256>>>(x);

    // h = x_mod @ w1^T + b1   (tf32 mma.sync)
    mm_gemm<0><<<dim3(LTOK / BM, N1 / BN), 256, GEMM_SMEM>>>(
        p_xmod, w1, p_h, N1, DMODEL, b1, nullptr, nullptr);

    qkv_prep<<<dim3(LTOK, NHEAD), 128>>>(pe, qsc, ksc);
    flash_k<<<dim3(LTOK / 64, NHEAD), 256, FLASH_SMEM>>>();
    gelu_cat<<<(LTOK * (MLPD / 4)) / 256, 256>>>();

    // out = x + gate * (cat @ w2^T + b2)   (tf32 mma.sync)
    mm_gemm<1><<<dim3(LTOK / BM, DMODEL / BN), 256, GEMM_SMEM>>>(
        p_cat, w2, out, DMODEL, K2, b2, x, p_m + 2 * DMODEL);
}

// round 4
// speedup vs baseline: 3.6042x; 1.6700x over previous
#include <cuda_runtime.h>
#include <math.h>
#include <stdint.h>

// ---------------------------------------------------------------------------
// Problem constants (B = 1)
// ---------------------------------------------------------------------------
#define LTOK 4096
#define DMODEL 3072
#define NHEAD 24
#define HDIM 128
#define MLPD 12288
#define N1 (3 * DMODEL + MLPD)   // 21504
#define K2 (DMODEL + MLPD)       // 15360
#define EPSV 1e-6f
#define SM_SCALE 0.08838834764831843f

// ---------------------------------------------------------------------------
// Scratch
// ---------------------------------------------------------------------------
__device__ float g_sv[DMODEL];
__device__ float g_m[3 * DMODEL];
__device__ float g_xmod[LTOK * DMODEL];
__device__ float g_h[LTOK * N1];
__device__ float g_q[NHEAD * LTOK * HDIM];
__device__ float g_k[NHEAD * LTOK * HDIM];
__device__ float g_v[NHEAD * LTOK * HDIM];
__device__ float g_cat[LTOK * K2];
__device__ float g_w1[(size_t)N1 * DMODEL];    // tf32-rounded w1
__device__ float g_w2[(size_t)DMODEL * K2];    // tf32-rounded w2

// ---------------------------------------------------------------------------
// helpers (sm_80-era PTX only: cp.async + mma.sync -- safe for plain sm_103)
// ---------------------------------------------------------------------------
__device__ __forceinline__ uint32_t smem_u32(const void* p) {
    uint32_t a;
    asm("{ .reg .u64 t; cvta.to.shared.u64 t, %1; cvt.u32.u64 %0, t; }"
        : "=r"(a) : "l"(p));
    return a;
}
__device__ __forceinline__ void cp_async16(uint32_t s, const void* g) {
    asm volatile("cp.async.cg.shared.global [%0], [%1], 16;" :: "r"(s), "l"(g) : "memory");
}
__device__ __forceinline__ uint32_t tf32_bits(float x) {
    uint32_t r;
    asm("{ .reg .b32 t; cvt.rna.tf32.f32 t, %1; mov.b32 %0, t; }" : "=r"(r) : "f"(x));
    return r;
}
__device__ __forceinline__ float tf32f(float x) {
    float r;
    asm("cvt.rna.tf32.f32 %0, %1;" : "=f"(r) : "f"(x));
    return r;
}
__device__ __forceinline__ void mma_tf32(float* c, const uint32_t* a, const uint32_t* b) {
    asm volatile(
        "mma.sync.aligned.m16n8k8.row.col.f32.tf32.tf32.f32 "
        "{%0,%1,%2,%3}, {%4,%5,%6,%7}, {%8,%9}, {%0,%1,%2,%3};"
        : "+f"(c[0]), "+f"(c[1]), "+f"(c[2]), "+f"(c[3])
        : "r"(a[0]), "r"(a[1]), "r"(a[2]), "r"(a[3]), "r"(b[0]), "r"(b[1]));
}
__device__ __forceinline__ void mma_tf32v(float* c, const uint32_t* a,
                                          uint32_t b0, uint32_t b1) {
    asm volatile(
        "mma.sync.aligned.m16n8k8.row.col.f32.tf32.tf32.f32 "
        "{%0,%1,%2,%3}, {%4,%5,%6,%7}, {%8,%9}, {%0,%1,%2,%3};"
        : "+f"(c[0]), "+f"(c[1]), "+f"(c[2]), "+f"(c[3])
        : "r"(a[0]), "r"(a[1]), "r"(a[2]), "r"(a[3]), "r"(b0), "r"(b1));
}

// ---------------------------------------------------------------------------
// small kernels
// ---------------------------------------------------------------------------
__global__ void silu_k(const float* __restrict__ vec) {
    int i = blockIdx.x * blockDim.x + threadIdx.x;
    if (i < DMODEL) {
        float v = vec[i];
        g_sv[i] = v / (1.0f + expf(-v));
    }
}

__global__ void mod_gemv(const float* __restrict__ mw, const float* __restrict__ mb) {
    int j = blockIdx.x * 8 + (threadIdx.x >> 5);
    int lane = threadIdx.x & 31;
    const float* wr = mw + (size_t)j * DMODEL;
    float s = 0.f;
    for (int k = lane; k < DMODEL; k += 32) s += g_sv[k] * wr[k];
#pragma unroll
    for (int o = 16; o; o >>= 1) s += __shfl_down_sync(0xffffffffu, s, o);
    if (lane == 0) g_m[j] = s + mb[j];
}

__device__ __forceinline__ float block_sum256(float v, float* buf) {
#pragma unroll
    for (int o = 16; o; o >>= 1) v += __shfl_down_sync(0xffffffffu, v, o);
    int w = threadIdx.x >> 5;
    if ((threadIdx.x & 31) == 0) buf[w] = v;
    __syncthreads();
    float s = 0.f;
#pragma unroll
    for (int i = 0; i < 8; i++) s += buf[i];
    return s;
}

__global__ void __launch_bounds__(256) ln_mod(const float* __restrict__ x) {
    __shared__ float xs[DMODEL];
    __shared__ float rbuf[8];
    int row = blockIdx.x;
    const float* xr = x + (size_t)row * DMODEL;
    float s = 0.f;
    for (int i = threadIdx.x; i < DMODEL; i += 256) {
        float v = xr[i];
        xs[i] = v;
        s += v;
    }
    float mu = block_sum256(s, rbuf) * (1.0f / DMODEL);
    __syncthreads();
    float s2 = 0.f;
    for (int i = threadIdx.x; i < DMODEL; i += 256) {
        float d = xs[i] - mu;
        s2 += d * d;
    }
    float var = block_sum256(s2, rbuf) * (1.0f / DMODEL);
    float rstd = rsqrtf(var + EPSV);
    float* xm = g_xmod + (size_t)row * DMODEL;
    for (int i = threadIdx.x; i < DMODEL; i += 256) {
        float n = (xs[i] - mu) * rstd;
        xm[i] = tf32f((1.0f + g_m[DMODEL + i]) * n + g_m[i]);   // GEMM1 A operand
    }
}

__global__ void __launch_bounds__(256) cvt_tf32_k(const float* __restrict__ src,
                                                  float* __restrict__ dst, int n4) {
    int i = blockIdx.x * 256 + threadIdx.x;
    if (i < n4) {
        float4 v = ((const float4*)src)[i];
        v.x = tf32f(v.x); v.y = tf32f(v.y);
        v.z = tf32f(v.z); v.w = tf32f(v.w);
        ((float4*)dst)[i] = v;
    }
}

// ---------------------------------------------------------------------------
// tf32 mma.sync GEMM (NT): operands pre-rounded to tf32 in memory.
// 128x128 CTA tile, 8 warps (2x4), each warp 64x32. BK=16, 3-stage cp.async.
// ---------------------------------------------------------------------------
#define BM 128
#define BN 128
#define BK 16
#define NSTG 3
#define SROW 20
#define TILE_FLOATS (BM * SROW)
#define GEMM_SMEM (NSTG * 2 * TILE_FLOATS * 4)

__device__ __forceinline__ void ld_stage(uint32_t As, uint32_t Bs,
                                         const float* __restrict__ Ag,
                                         const float* __restrict__ Bg,
                                         int K, int kb, int tid) {
#pragma unroll
    for (int it = 0; it < 2; ++it) {
        int id = it * 256 + tid;
        int row = id >> 2, c4 = id & 3;
        uint32_t off = (uint32_t)(row * SROW + c4 * 4) * 4u;
        const size_t goff = (size_t)row * K + kb + c4 * 4;
        cp_async16(As + off, Ag + goff);
        cp_async16(Bs + off, Bg + goff);
    }
}

template <int EPI>
__global__ void __launch_bounds__(256, 2)
mm_gemm(const float* __restrict__ A, const float* __restrict__ B,
        float* __restrict__ C, int Nt, int K,
        const float* __restrict__ bias,
        const float* __restrict__ xres, const float* __restrict__ gate) {
    extern __shared__ float smf[];
    const uint32_t sA = smem_u32(smf);
    const uint32_t sB = sA + NSTG * TILE_FLOATS * 4;

    const int tid = threadIdx.x;
    const int wid = tid >> 5, lane = tid & 31;
    const int gp = lane >> 2, qd = lane & 3;
    const int warpM = (wid >> 2) * 64;
    const int warpN = (wid & 3) * 32;
    const int bm = blockIdx.x * BM;
    const int bn = blockIdx.y * BN;

    const float* Ag = A + (size_t)bm * K;
    const float* Bg = B + (size_t)bn * K;
    const int nch = K / BK;

    float acc[4][4][4] = {};

    ld_stage(sA, sB, Ag, Bg, K, 0, tid);
    asm volatile("cp.async.commit_group;" ::: "memory");
    ld_stage(sA + TILE_FLOATS * 4, sB + TILE_FLOATS * 4, Ag, Bg, K, BK, tid);
    asm volatile("cp.async.commit_group;" ::: "memory");

    for (int j = 0; j < nch; ++j) {
        const int c = j + 2;
        if (c < nch) {
            const int st = c % NSTG;
            ld_stage(sA + st * TILE_FLOATS * 4, sB + st * TILE_FLOATS * 4,
                     Ag, Bg, K, c * BK, tid);
        }
        asm volatile("cp.async.commit_group;" ::: "memory");
        asm volatile("cp.async.wait_group 1;" ::: "memory");
        __syncthreads();

        const float* as = smf + (j % NSTG) * TILE_FLOATS;
        const float* bs = smf + NSTG * TILE_FLOATS + (j % NSTG) * TILE_FLOATS;
#pragma unroll
        for (int ks = 0; ks < 2; ++ks) {
            uint32_t af[4][4], bf[4][2];
#pragma unroll
            for (int mt = 0; mt < 4; ++mt) {
                const float* p = as + (warpM + mt * 16 + gp) * SROW + ks * 8 + qd;
                af[mt][0] = __float_as_uint(p[0]);
                af[mt][1] = __float_as_uint(p[8 * SROW]);
                af[mt][2] = __float_as_uint(p[4]);
                af[mt][3] = __float_as_uint(p[8 * SROW + 4]);
            }
#pragma unroll
            for (int nt = 0; nt < 4; ++nt) {
                const float* p = bs + (warpN + nt * 8 + gp) * SROW + ks * 8 + qd;
                bf[nt][0] = __float_as_uint(p[0]);
                bf[nt][1] = __float_as_uint(p[4]);
            }
#pragma unroll
            for (int mt = 0; mt < 4; ++mt)
#pragma unroll
                for (int nt = 0; nt < 4; ++nt)
                    mma_tf32(acc[mt][nt], af[mt], bf[nt]);
        }
        __syncthreads();
    }

#pragma unroll
    for (int nt = 0; nt < 4; ++nt) {
        const int col = bn + warpN + nt * 8 + 2 * qd;
        const float b0 = bias[col], b1 = bias[col + 1];
        float g0 = 0.f, g1 = 0.f;
        if (EPI) { g0 = gate[col]; g1 = gate[col + 1]; }
#pragma unroll
        for (int mt = 0; mt < 4; ++mt) {
            const int r0 = bm + warpM + mt * 16 + gp;
#pragma unroll
            for (int half = 0; half < 2; ++half) {
                const int row = r0 + half * 8;
                float v0 = acc[mt][nt][half * 2 + 0] + b0;
                float v1 = acc[mt][nt][half * 2 + 1] + b1;
                const size_t off = (size_t)row * Nt + col;
                if (EPI) {
                    float2 xr = *(const float2*)(xres + off);
                    v0 = xr.x + g0 * v0;
                    v1 = xr.y + g1 * v1;
                }
                *(float2*)(C + off) = make_float2(v0, v1);
            }
        }
    }
}

// ---------------------------------------------------------------------------
// QKV prep: RMSNorm + RoPE + head-major relayout; k,v tf32-rounded (q rounded
// in flash after SM_SCALE).
// ---------------------------------------------------------------------------
__global__ void __launch_bounds__(128)
qkv_prep(const float* __restrict__ pe,
         const float* __restrict__ q_scale, const float* __restrict__ k_scale) {
    int i = blockIdx.x;
    int hh = blockIdx.y;
    int d = threadIdx.x;

    const float* hp = g_h + (size_t)i * N1 + hh * HDIM;
    float qv = hp[d];
    float kv = hp[DMODEL + d];
    float vv = hp[2 * DMODEL + d];

    __shared__ float rb[2][4];
    float sq = qv * qv, sk = kv * kv;
#pragma unroll
    for (int o = 16; o; o >>= 1) {
        sq += __shfl_down_sync(0xffffffffu, sq, o);
        sk += __shfl_down_sync(0xffffffffu, sk, o);
    }
    if ((d & 31) == 0) { rb[0][d >> 5] = sq; rb[1][d >> 5] = sk; }
    __syncthreads();
    float ssq = rb[0][0] + rb[0][1] + rb[0][2] + rb[0][3];
    float ssk = rb[1][0] + rb[1][1] + rb[1][2] + rb[1][3];
    float rq = rsqrtf(ssq * (1.0f / HDIM) + EPSV);
    float rk = rsqrtf(ssk * (1.0f / HDIM) + EPSV);

    float qn = qv * rq * q_scale[d];
    float kn = kv * rk * k_scale[d];

    int e = d >> 1;
    int base = (i * (HDIM / 2) + e) * 4 + (d & 1) * 2;
    float p0 = pe[base], p1 = pe[base + 1];
    float qp = __shfl_xor_sync(0xffffffffu, qn, 1);
    float kp = __shfl_xor_sync(0xffffffffu, kn, 1);
    float qe = (d & 1) ? qp : qn, qo = (d & 1) ? qn : qp;
    float ke = (d & 1) ? kp : kn, ko = (d & 1) ? kn : kp;
    float qr = p0 * qe + p1 * qo;
    float kr = p0 * ke + p1 * ko;

    size_t o = ((size_t)hh * LTOK + i) * HDIM + d;
    g_q[o] = qr;
    g_k[o] = tf32f(kr);
    g_v[o] = tf32f(vv);
}

// ---------------------------------------------------------------------------
// Flash attention, tf32 mma.sync. 256 threads / 8 warps. Q tile 128 (16/warp),
// KV tiles 64, double-buffered cp.async. Fragment layouts identical to mm_gemm
// (validated). Output -> g_cat[:, h*128...], tf32-rounded (GEMM2 A operand).
// ---------------------------------------------------------------------------
#define KS_STRIDE 132
#define VS_STRIDE 136
#define PS_STRIDE 68
#define FL_SMEM ((2 * 64 * KS_STRIDE + 2 * 64 * VS_STRIDE + 128 * PS_STRIDE) * 4)

__device__ __forceinline__ void load_kv(float* Ksm, float* Vsm,
                                        const float* __restrict__ Kg,
                                        const float* __restrict__ Vg,
                                        int kt, int buf, int tid) {
    uint32_t kd = smem_u32(Ksm + buf * 64 * KS_STRIDE);
    uint32_t vd = smem_u32(Vsm + buf * 64 * VS_STRIDE);
#pragma unroll
    for (int it = 0; it < 8; ++it) {
        int id = it * 256 + tid;
        int row = id >> 5, c4 = (id & 31) * 4;
        cp_async16(kd + (uint32_t)(row * KS_STRIDE + c4) * 4,
                   Kg + (size_t)(kt + row) * HDIM + c4);
        cp_async16(vd + (uint32_t)(row * VS_STRIDE + c4) * 4,
                   Vg + (size_t)(kt + row) * HDIM + c4);
    }
}

__global__ void __launch_bounds__(256, 1) flash_tc() {
    extern __shared__ float sm[];
    float* Ksm = sm;                                   // [2][64][132]
    float* Vsm = Ksm + 2 * 64 * KS_STRIDE;             // [2][64][136]
    float* Ps  = Vsm + 2 * 64 * VS_STRIDE;             // [128][68]

    const int h = blockIdx.y;
    const int qb = blockIdx.x * 128;
    const int tid = threadIdx.x;
    const int w = tid >> 5, lane = tid & 31;
    const int gp = lane >> 2, qd = lane & 3;

    const float* Qg = g_q + ((size_t)h * LTOK + qb) * HDIM;
    const float* Kg = g_k + (size_t)h * LTOK * HDIM;
    const float* Vg = g_v + (size_t)h * LTOK * HDIM;

    // Q fragments in registers (scaled + tf32-rounded), rows w*16+gp, +8
    uint32_t qf[16][4];
    {
        const float* q0 = Qg + (w * 16 + gp) * HDIM;
        const float* q1 = q0 + 8 * HDIM;
#pragma unroll
        for (int ks = 0; ks < 16; ++ks) {
            int c = ks * 8 + qd;
            qf[ks][0] = tf32_bits(q0[c] * SM_SCALE);
            qf[ks][1] = tf32_bits(q1[c] * SM_SCALE);
            qf[ks][2] = tf32_bits(q0[c + 4] * SM_SCALE);
            qf[ks][3] = tf32_bits(q1[c + 4] * SM_SCALE);
        }
    }

    float ofr[16][4] = {};
    float m0 = -1e30f, m1 = -1e30f, l0 = 0.f, l1 = 0.f;

    load_kv(Ksm, Vsm, Kg, Vg, 0, 0, tid);
    asm volatile("cp.async.commit_group;" ::: "memory");

    float* pw = Ps + (w * 16 + gp) * PS_STRIDE;

    for (int t = 0; t < LTOK / 64; ++t) {
        const int buf = t & 1;
        asm volatile("cp.async.wait_group 0;" ::: "memory");
        __syncthreads();
        if (t + 1 < LTOK / 64)
            load_kv(Ksm, Vsm, Kg, Vg, (t + 1) * 64, buf ^ 1, tid);
        asm volatile("cp.async.commit_group;" ::: "memory");

        const float* kb = Ksm + buf * 64 * KS_STRIDE;
        const float* vb = Vsm + buf * 64 * VS_STRIDE;

        // S = Q K^T : per-warp 16x64
        float sfr[8][4] = {};
#pragma unroll
        for (int ks = 0; ks < 16; ++ks) {
#pragma unroll
            for (int nt = 0; nt < 8; ++nt) {
                const float* p = kb + (nt * 8 + gp) * KS_STRIDE + ks * 8 + qd;
                mma_tf32v(sfr[nt], qf[ks],
                          __float_as_uint(p[0]), __float_as_uint(p[4]));
            }
        }

        // online softmax (rows gp, gp+8 of this warp's block)
        float mx0 = -1e30f, mx1 = -1e30f;
#pragma unroll
        for (int nt = 0; nt < 8; ++nt) {
            mx0 = fmaxf(mx0, fmaxf(sfr[nt][0], sfr[nt][1]));
            mx1 = fmaxf(mx1, fmaxf(sfr[nt][2], sfr[nt][3]));
        }
        mx0 = fmaxf(mx0, __shfl_xor_sync(0xffffffffu, mx0, 1));
        mx0 = fmaxf(mx0, __shfl_xor_sync(0xffffffffu, mx0, 2));
        mx1 = fmaxf(mx1, __shfl_xor_sync(0xffffffffu, mx1, 1));
        mx1 = fmaxf(mx1, __shfl_xor_sync(0xffffffffu, mx1, 2));
        float mn0 = fmaxf(m0, mx0), mn1 = fmaxf(m1, mx1);
        float a0 = __expf(m0 - mn0), a1 = __expf(m1 - mn1);
        m0 = mn0; m1 = mn1;

        float rs0 = 0.f, rs1 = 0.f;
#pragma unroll
        for (int nt = 0; nt < 8; ++nt) {
            float p00 = __expf(sfr[nt][0] - mn0);
            float p01 = __expf(sfr[nt][1] - mn0);
            float p10 = __expf(sfr[nt][2] - mn1);
            float p11 = __expf(sfr[nt][3] - mn1);
            rs0 += p00 + p01;
            rs1 += p10 + p11;
            int c = nt * 8 + 2 * qd;
            *(float2*)(pw + c) = make_float2(tf32f(p00), tf32f(p01));
            *(float2*)(pw + 8 * PS_STRIDE + c) = make_float2(tf32f(p10), tf32f(p11));
        }
        rs0 += __shfl_xor_sync(0xffffffffu, rs0, 1);
        rs0 += __shfl_xor_sync(0xffffffffu, rs0, 2);
        rs1 += __shfl_xor_sync(0xffffffffu, rs1, 1);
        rs1 += __shfl_xor_sync(0xffffffffu, rs1, 2);
        l0 = l0 * a0 + rs0;
        l1 = l1 * a1 + rs1;

#pragma unroll
        for (int nt = 0; nt < 16; ++nt) {
            ofr[nt][0] *= a0; ofr[nt][1] *= a0;
            ofr[nt][2] *= a1; ofr[nt][3] *= a1;
        }
        __syncwarp();

        // O += P @ V
#pragma unroll
        for (int ks2 = 0; ks2 < 8; ++ks2) {
            uint32_t pf[4];
            pf[0] = __float_as_uint(pw[ks2 * 8 + qd]);
            pf[1] = __float_as_uint(pw[8 * PS_STRIDE + ks2 * 8 + qd]);
            pf[2] = __float_as_uint(pw[ks2 * 8 + qd + 4]);
            pf[3] = __float_as_uint(pw[8 * PS_STRIDE + ks2 * 8 + qd + 4]);
#pragma unroll
            for (int nt = 0; nt < 16; ++nt) {
                const float* vp = vb + (ks2 * 8 + qd) * VS_STRIDE + nt * 8 + gp;
                mma_tf32v(ofr[nt], pf,
                          __float_as_uint(vp[0]),
                          __float_as_uint(vp[4 * VS_STRIDE]));
            }
        }
    }

    // finalize
    float inv0 = 1.0f / l0, inv1 = 1.0f / l1;
    float* o0 = g_cat + (size_t)(qb + w * 16 + gp) * K2 + h * HDIM;
    float* o1 = o0 + (size_t)8 * K2;
#pragma unroll
    for (int nt = 0; nt < 16; ++nt) {
        int c = nt * 8 + 2 * qd;
        *(float2*)(o0 + c) = make_float2(tf32f(ofr[nt][0] * inv0),
                                         tf32f(ofr[nt][1] * inv0));
        *(float2*)(o1 + c) = make_float2(tf32f(ofr[nt][2] * inv1),
                                         tf32f(ofr[nt][3] * inv1));
    }
}

// ---------------------------------------------------------------------------
// gelu(mlp) into concat buffer, tf32-rounded (GEMM2 A operand)
// ---------------------------------------------------------------------------
__device__ __forceinline__ float gelu_t(float x) {
    return 0.5f * x * (1.0f + tanhf(0.7978845608028654f * (x + 0.044715f * x * x * x)));
}

__global__ void __launch_bounds__(256) gelu_cat() {
    int idx = blockIdx.x * 256 + threadIdx.x;
    const int per_row = MLPD / 4;
    if (idx >= LTOK * per_row) return;
    int row = idx / per_row;
    int c4 = idx - row * per_row;
    float4 v = *(const float4*)(g_h + (size_t)row * N1 + 3 * DMODEL + c4 * 4);
    float4 r;
    r.x = tf32f(gelu_t(v.x)); r.y = tf32f(gelu_t(v.y));
    r.z = tf32f(gelu_t(v.z)); r.w = tf32f(gelu_t(v.w));
    *(float4*)(g_cat + (size_t)row * K2 + DMODEL + c4 * 4) = r;
}

// ---------------------------------------------------------------------------
// launch
// ---------------------------------------------------------------------------
extern "C" void kernel_launch(void* const* d_in, const int* in_sizes, int n_in,
                              void* d_out, int out_size) {
    const float* x   = (const float*)d_in[0];
    const float* vec = (const float*)d_in[1];
    const float* pe  = (const float*)d_in[2];
    const float* w1  = (const float*)d_in[3];
    const float* b1  = (const float*)d_in[4];
    const float* w2  = (const float*)d_in[5];
    const float* b2  = (const float*)d_in[6];
    const float* mw  = (const float*)d_in[7];
    const float* mb  = (const float*)d_in[8];
    const float* qsc = (const float*)d_in[9];
    const float* ksc = (const float*)d_in[10];
    float* out = (float*)d_out;

    float *p_xmod, *p_h, *p_cat, *p_m, *p_w1, *p_w2;
    cudaGetSymbolAddress((void**)&p_xmod, g_xmod);
    cudaGetSymbolAddress((void**)&p_h, g_h);
    cudaGetSymbolAddress((void**)&p_cat, g_cat);
    cudaGetSymbolAddress((void**)&p_m, g_m);
    cudaGetSymbolAddress((void**)&p_w1, g_w1);
    cudaGetSymbolAddress((void**)&p_w2, g_w2);

    cudaFuncSetAttribute(flash_tc, cudaFuncAttributeMaxDynamicSharedMemorySize, FL_SMEM);
    cudaFuncSetAttribute(mm_gemm<0>, cudaFuncAttributeMaxDynamicSharedMemorySize, GEMM_SMEM);
    cudaFuncSetAttribute(mm_gemm<1>, cudaFuncAttributeMaxDynamicSharedMemorySize, GEMM_SMEM);

    silu_k<<<(DMODEL + 255) / 256, 256>>>(vec);
    mod_gemv<<<(3 * DMODEL) / 8, 256>>>(mw, mb);
    ln_mod<<<LTOK, 256>>>(x);

    // tf32-round the weights once (B operands)
    {
        int n4 = (N1 * DMODEL) / 4;
        cvt_tf32_k<<<(n4 + 255) / 256, 256>>>(w1, p_w1, n4);
        n4 = (DMODEL * K2) / 4;
        cvt_tf32_k<<<(n4 + 255) / 256, 256>>>(w2, p_w2, n4);
    }

    // h = x_mod @ w1^T + b1
    mm_gemm<0><<<dim3(LTOK / BM, N1 / BN), 256, GEMM_SMEM>>>(
        p_xmod, p_w1, p_h, N1, DMODEL, b1, nullptr, nullptr);

    qkv_prep<<<dim3(LTOK, NHEAD), 128>>>(pe, qsc, ksc);
    flash_tc<<<dim3(LTOK / 128, NHEAD), 256, FL_SMEM>>>();
    gelu_cat<<<(LTOK * (MLPD / 4)) / 256, 256>>>();

    // out = x + gate * (cat @ w2^T + b2)
    mm_gemm<1><<<dim3(LTOK / BM, DMODEL / BN), 256, GEMM_SMEM>>>(
        p_cat, p_w2, out, DMODEL, K2, b2, x, p_m + 2 * DMODEL);
}

// round 5
// speedup vs baseline: 6.9987x; 1.9418x over previous
#include <cuda_runtime.h>
#include <cuda_fp16.h>
#include <math.h>
#include <stdint.h>

// ---------------------------------------------------------------------------
// Problem constants (B = 1)
// ---------------------------------------------------------------------------
#define LTOK 4096
#define DMODEL 3072
#define NHEAD 24
#define HDIM 128
#define MLPD 12288
#define N1 (3 * DMODEL + MLPD)   // 21504
#define K2 (DMODEL + MLPD)       // 15360
#define EPSV 1e-6f
#define SM_SCALE 0.08838834764831843f

// ---------------------------------------------------------------------------
// Scratch
// ---------------------------------------------------------------------------
__device__ float  g_sv[DMODEL];
__device__ float  g_m[3 * DMODEL];
__device__ __half g_xmodh[LTOK * DMODEL];
__device__ float  g_h[(size_t)LTOK * N1];
__device__ __half g_qh[(size_t)NHEAD * LTOK * HDIM];   // pre-scaled by SM_SCALE
__device__ __half g_kh[(size_t)NHEAD * LTOK * HDIM];
__device__ __half g_vh[(size_t)NHEAD * LTOK * HDIM];
__device__ __half g_cath[(size_t)LTOK * K2];
__device__ __half g_w1h[(size_t)N1 * DMODEL];
__device__ __half g_w2h[(size_t)DMODEL * K2];

// ---------------------------------------------------------------------------
// helpers (sm_75/80-era PTX only: cp.async, mma.sync, ldmatrix)
// ---------------------------------------------------------------------------
__device__ __forceinline__ uint32_t smem_u32(const void* p) {
    uint32_t a;
    asm("{ .reg .u64 t; cvta.to.shared.u64 t, %1; cvt.u32.u64 %0, t; }"
        : "=r"(a) : "l"(p));
    return a;
}
__device__ __forceinline__ void cp_async16(uint32_t s, const void* g) {
    asm volatile("cp.async.cg.shared.global [%0], [%1], 16;" :: "r"(s), "l"(g) : "memory");
}
__device__ __forceinline__ void mma_f16(float* c, const uint32_t* a,
                                        uint32_t b0, uint32_t b1) {
    asm volatile(
        "mma.sync.aligned.m16n8k16.row.col.f32.f16.f16.f32 "
        "{%0,%1,%2,%3}, {%4,%5,%6,%7}, {%8,%9}, {%0,%1,%2,%3};"
        : "+f"(c[0]), "+f"(c[1]), "+f"(c[2]), "+f"(c[3])
        : "r"(a[0]), "r"(a[1]), "r"(a[2]), "r"(a[3]), "r"(b0), "r"(b1));
}
__device__ __forceinline__ void ldsm4(uint32_t* r, uint32_t addr) {
    asm volatile("ldmatrix.sync.aligned.m8n8.x4.shared.b16 {%0,%1,%2,%3}, [%4];"
                 : "=r"(r[0]), "=r"(r[1]), "=r"(r[2]), "=r"(r[3]) : "r"(addr));
}
__device__ __forceinline__ void ldsm4t(uint32_t* r, uint32_t addr) {
    asm volatile("ldmatrix.sync.aligned.m8n8.x4.trans.shared.b16 {%0,%1,%2,%3}, [%4];"
                 : "=r"(r[0]), "=r"(r[1]), "=r"(r[2]), "=r"(r[3]) : "r"(addr));
}
__device__ __forceinline__ uint32_t packh2(float lo, float hi) {
    __half2 h = __floats2half2_rn(lo, hi);
    return *reinterpret_cast<uint32_t*>(&h);
}

// ---------------------------------------------------------------------------
// small kernels
// ---------------------------------------------------------------------------
__global__ void silu_k(const float* __restrict__ vec) {
    int i = blockIdx.x * blockDim.x + threadIdx.x;
    if (i < DMODEL) {
        float v = vec[i];
        g_sv[i] = v / (1.0f + expf(-v));
    }
}

__global__ void mod_gemv(const float* __restrict__ mw, const float* __restrict__ mb) {
    int j = blockIdx.x * 8 + (threadIdx.x >> 5);
    int lane = threadIdx.x & 31;
    const float* wr = mw + (size_t)j * DMODEL;
    float s = 0.f;
    for (int k = lane; k < DMODEL; k += 32) s += g_sv[k] * wr[k];
#pragma unroll
    for (int o = 16; o; o >>= 1) s += __shfl_down_sync(0xffffffffu, s, o);
    if (lane == 0) g_m[j] = s + mb[j];
}

__device__ __forceinline__ float block_sum256(float v, float* buf) {
#pragma unroll
    for (int o = 16; o; o >>= 1) v += __shfl_down_sync(0xffffffffu, v, o);
    int w = threadIdx.x >> 5;
    if ((threadIdx.x & 31) == 0) buf[w] = v;
    __syncthreads();
    float s = 0.f;
#pragma unroll
    for (int i = 0; i < 8; i++) s += buf[i];
    return s;
}

__global__ void __launch_bounds__(256) ln_mod(const float* __restrict__ x) {
    __shared__ float xs[DMODEL];
    __shared__ float rbuf[8];
    int row = blockIdx.x;
    const float* xr = x + (size_t)row * DMODEL;
    float s = 0.f;
    for (int i = threadIdx.x; i < DMODEL; i += 256) {
        float v = xr[i];
        xs[i] = v;
        s += v;
    }
    float mu = block_sum256(s, rbuf) * (1.0f / DMODEL);
    __syncthreads();
    float s2 = 0.f;
    for (int i = threadIdx.x; i < DMODEL; i += 256) {
        float d = xs[i] - mu;
        s2 += d * d;
    }
    float var = block_sum256(s2, rbuf) * (1.0f / DMODEL);
    float rstd = rsqrtf(var + EPSV);
    __half* xm = g_xmodh + (size_t)row * DMODEL;
    for (int i = threadIdx.x; i < DMODEL; i += 256) {
        float n = (xs[i] - mu) * rstd;
        xm[i] = __float2half_rn((1.0f + g_m[DMODEL + i]) * n + g_m[i]);
    }
}

// fp32 -> fp16 weight conversion
__global__ void __launch_bounds__(256) cvt_h_k(const float* __restrict__ src,
                                               __half* __restrict__ dst, int n4) {
    int i = blockIdx.x * 256 + threadIdx.x;
    if (i < n4) {
        float4 v = ((const float4*)src)[i];
        uint2 u = make_uint2(packh2(v.x, v.y), packh2(v.z, v.w));
        *(uint2*)(dst + (size_t)i * 4) = u;
    }
}

// ---------------------------------------------------------------------------
// fp16 mma.sync GEMM (NT): C[M,Nt] = A[M,K] @ B[Nt,K]^T (+bias, opt epilogue)
// 128x128 CTA tile, 8 warps (2x4), each warp 64x32. BK=32 halves, 3 stages.
// ---------------------------------------------------------------------------
#define BM 128
#define BN 128
#define BK 32
#define NSTG 3
#define AROWH 40                          // 32 data halves + 8 pad
#define TILEH (BM * AROWH)                // halves per operand tile
#define GEMM_SMEM (NSTG * 2 * TILEH * 2)  // 61440 B

__device__ __forceinline__ void ld_stage(uint32_t As, uint32_t Bs,
                                         const __half* __restrict__ Ag,
                                         const __half* __restrict__ Bg,
                                         int K, int kb, int tid) {
#pragma unroll
    for (int it = 0; it < 2; ++it) {
        int id = it * 256 + tid;                 // 512 16B chunks per operand
        int row = id >> 2, c = id & 3;
        uint32_t off = (uint32_t)(row * AROWH * 2 + c * 16);
        const size_t goff = (size_t)row * K + kb + c * 8;
        cp_async16(As + off, Ag + goff);
        cp_async16(Bs + off, Bg + goff);
    }
}

template <int EPI>
__global__ void __launch_bounds__(256, 2)
mm_gemm(const __half* __restrict__ A, const __half* __restrict__ B,
        float* __restrict__ C, int Nt, int K,
        const float* __restrict__ bias,
        const float* __restrict__ xres, const float* __restrict__ gate) {
    extern __shared__ __half smh[];
    const uint32_t sA = smem_u32(smh);
    const uint32_t sB = sA + NSTG * TILEH * 2;

    const int tid = threadIdx.x;
    const int wid = tid >> 5, lane = tid & 31;
    const int gp = lane >> 2, qd = lane & 3;
    const int warpM = (wid >> 2) * 64;
    const int warpN = (wid & 3) * 32;
    const int bm = blockIdx.x * BM;
    const int bn = blockIdx.y * BN;

    const __half* Ag = A + (size_t)bm * K;
    const __half* Bg = B + (size_t)bn * K;
    const int nch = K / BK;

    float acc[4][4][4] = {};

    ld_stage(sA, sB, Ag, Bg, K, 0, tid);
    asm volatile("cp.async.commit_group;" ::: "memory");
    ld_stage(sA + TILEH * 2, sB + TILEH * 2, Ag, Bg, K, BK, tid);
    asm volatile("cp.async.commit_group;" ::: "memory");

    for (int j = 0; j < nch; ++j) {
        const int c = j + 2;
        if (c < nch) {
            const int st = c % NSTG;
            ld_stage(sA + st * TILEH * 2, sB + st * TILEH * 2,
                     Ag, Bg, K, c * BK, tid);
        }
        asm volatile("cp.async.commit_group;" ::: "memory");
        asm volatile("cp.async.wait_group 1;" ::: "memory");
        __syncthreads();

        const __half* as = smh + (j % NSTG) * TILEH;
        const __half* bs = smh + NSTG * TILEH + (j % NSTG) * TILEH;
#pragma unroll
        for (int ks = 0; ks < 2; ++ks) {
            uint32_t af[4][4], bf[4][2];
#pragma unroll
            for (int mt = 0; mt < 4; ++mt) {
                const __half* p = as + (warpM + mt * 16 + gp) * AROWH + ks * 16 + 2 * qd;
                af[mt][0] = *(const uint32_t*)p;
                af[mt][1] = *(const uint32_t*)(p + 8 * AROWH);
                af[mt][2] = *(const uint32_t*)(p + 8);
                af[mt][3] = *(const uint32_t*)(p + 8 * AROWH + 8);
            }
#pragma unroll
            for (int nt = 0; nt < 4; ++nt) {
                const __half* p = bs + (warpN + nt * 8 + gp) * AROWH + ks * 16 + 2 * qd;
                bf[nt][0] = *(const uint32_t*)p;
                bf[nt][1] = *(const uint32_t*)(p + 8);
            }
#pragma unroll
            for (int mt = 0; mt < 4; ++mt)
#pragma unroll
                for (int nt = 0; nt < 4; ++nt)
                    mma_f16(acc[mt][nt], af[mt], bf[nt][0], bf[nt][1]);
        }
        __syncthreads();
    }

#pragma unroll
    for (int nt = 0; nt < 4; ++nt) {
        const int col = bn + warpN + nt * 8 + 2 * qd;
        const float b0 = bias[col], b1 = bias[col + 1];
        float g0 = 0.f, g1 = 0.f;
        if (EPI) { g0 = gate[col]; g1 = gate[col + 1]; }
#pragma unroll
        for (int mt = 0; mt < 4; ++mt) {
            const int r0 = bm + warpM + mt * 16 + gp;
#pragma unroll
            for (int half = 0; half < 2; ++half) {
                const int row = r0 + half * 8;
                float v0 = acc[mt][nt][half * 2 + 0] + b0;
                float v1 = acc[mt][nt][half * 2 + 1] + b1;
                const size_t off = (size_t)row * Nt + col;
                if (EPI) {
                    float2 xr = *(const float2*)(xres + off);
                    v0 = xr.x + g0 * v0;
                    v1 = xr.y + g1 * v1;
                }
                *(float2*)(C + off) = make_float2(v0, v1);
            }
        }
    }
}

// ---------------------------------------------------------------------------
// QKV prep: RMSNorm + RoPE + head-major fp16 relayout (q pre-scaled)
// ---------------------------------------------------------------------------
__global__ void __launch_bounds__(128)
qkv_prep(const float* __restrict__ pe,
         const float* __restrict__ q_scale, const float* __restrict__ k_scale) {
    int i = blockIdx.x;
    int hh = blockIdx.y;
    int d = threadIdx.x;

    const float* hp = g_h + (size_t)i * N1 + hh * HDIM;
    float qv = hp[d];
    float kv = hp[DMODEL + d];
    float vv = hp[2 * DMODEL + d];

    __shared__ float rb[2][4];
    float sq = qv * qv, sk = kv * kv;
#pragma unroll
    for (int o = 16; o; o >>= 1) {
        sq += __shfl_down_sync(0xffffffffu, sq, o);
        sk += __shfl_down_sync(0xffffffffu, sk, o);
    }
    if ((d & 31) == 0) { rb[0][d >> 5] = sq; rb[1][d >> 5] = sk; }
    __syncthreads();
    float ssq = rb[0][0] + rb[0][1] + rb[0][2] + rb[0][3];
    float ssk = rb[1][0] + rb[1][1] + rb[1][2] + rb[1][3];
    float rq = rsqrtf(ssq * (1.0f / HDIM) + EPSV);
    float rk = rsqrtf(ssk * (1.0f / HDIM) + EPSV);

    float qn = qv * rq * q_scale[d];
    float kn = kv * rk * k_scale[d];

    int e = d >> 1;
    int base = (i * (HDIM / 2) + e) * 4 + (d & 1) * 2;
    float p0 = pe[base], p1 = pe[base + 1];
    float qp = __shfl_xor_sync(0xffffffffu, qn, 1);
    float kp = __shfl_xor_sync(0xffffffffu, kn, 1);
    float qe = (d & 1) ? qp : qn, qo = (d & 1) ? qn : qp;
    float ke = (d & 1) ? kp : kn, ko = (d & 1) ? kn : kp;
    float qr = p0 * qe + p1 * qo;
    float kr = p0 * ke + p1 * ko;

    size_t o = ((size_t)hh * LTOK + i) * HDIM + d;
    g_qh[o] = __float2half_rn(qr * SM_SCALE);
    g_kh[o] = __float2half_rn(kr);
    g_vh[o] = __float2half_rn(vv);
}

// ---------------------------------------------------------------------------
// Flash attention fp16 mma. 8 warps, Q tile 128 (16 rows/warp in regs),
// KV tile 64 double-buffered cp.async. P kept in registers (C->A frag reuse).
// V consumed via ldmatrix.trans. Output -> g_cath fp16.
// ---------------------------------------------------------------------------
#define KSH 136                                   // halves per smem row
#define KVBUF (64 * KSH * 2)                      // bytes per tensor per buffer
#define FL_SMEM (4 * KVBUF)                       // K x2 bufs + V x2 bufs

__device__ __forceinline__ void load_kv(uint32_t kd, uint32_t vd,
                                        const __half* __restrict__ Kg,
                                        const __half* __restrict__ Vg,
                                        int kt, int tid) {
#pragma unroll
    for (int it = 0; it < 4; ++it) {
        int id = it * 256 + tid;                  // 1024 chunks per tensor
        int row = id >> 4, c = id & 15;
        uint32_t off = (uint32_t)(row * KSH * 2 + c * 16);
        const size_t goff = (size_t)(kt + row) * HDIM + c * 8;
        cp_async16(kd + off, Kg + goff);
        cp_async16(vd + off, Vg + goff);
    }
}

__global__ void __launch_bounds__(256, 1) flash_h() {
    extern __shared__ __half smh[];
    const uint32_t kbase0 = smem_u32(smh);
    const uint32_t vbase0 = kbase0 + 2 * KVBUF;

    const int h = blockIdx.y;
    const int qb = blockIdx.x * 128;
    const int tid = threadIdx.x;
    const int w = tid >> 5, lane = tid & 31;
    const int gp = lane >> 2, qd = lane & 3;

    const __half* Kg = g_kh + (size_t)h * LTOK * HDIM;
    const __half* Vg = g_vh + (size_t)h * LTOK * HDIM;

    // Q fragments in registers (rows w*16+gp, +8), pre-scaled fp16
    uint32_t qf[8][4];
    {
        const __half* q0 = g_qh + ((size_t)h * LTOK + qb + w * 16 + gp) * HDIM;
        const __half* q1 = q0 + 8 * HDIM;
#pragma unroll
        for (int ks = 0; ks < 8; ++ks) {
            int c = ks * 16 + 2 * qd;
            qf[ks][0] = *(const uint32_t*)(q0 + c);
            qf[ks][1] = *(const uint32_t*)(q1 + c);
            qf[ks][2] = *(const uint32_t*)(q0 + c + 8);
            qf[ks][3] = *(const uint32_t*)(q1 + c + 8);
        }
    }

    float ofr[16][4] = {};
    float m0 = -1e30f, m1 = -1e30f, l0 = 0.f, l1 = 0.f;

    load_kv(kbase0, vbase0, Kg, Vg, 0, tid);
    asm volatile("cp.async.commit_group;" ::: "memory");

    const int nT = LTOK / 64;
    for (int t = 0; t < nT; ++t) {
        const int buf = t & 1;
        asm volatile("cp.async.wait_group 0;" ::: "memory");
        __syncthreads();
        if (t + 1 < nT)
            load_kv(kbase0 + (buf ^ 1) * KVBUF, vbase0 + (buf ^ 1) * KVBUF,
                    Kg, Vg, (t + 1) * 64, tid);
        asm volatile("cp.async.commit_group;" ::: "memory");

        const uint32_t kb = kbase0 + buf * KVBUF;
        const uint32_t vb = vbase0 + buf * KVBUF;

        // S = Q K^T : per-warp 16x64 (fp32 frags)
        float sfr[8][4] = {};
#pragma unroll
        for (int nt = 0; nt < 8; ++nt) {
            uint32_t bb[8][2];
#pragma unroll
            for (int j = 0; j < 4; ++j) {
                uint32_t ad = kb + (uint32_t)(((nt * 8 + (lane & 7)) * KSH +
                                               j * 32 + (lane >> 3) * 8) * 2);
                uint32_t r[4];
                ldsm4(r, ad);
                bb[2 * j][0] = r[0]; bb[2 * j][1] = r[1];
                bb[2 * j + 1][0] = r[2]; bb[2 * j + 1][1] = r[3];
            }
#pragma unroll
            for (int ks = 0; ks < 8; ++ks)
                mma_f16(sfr[nt], qf[ks], bb[ks][0], bb[ks][1]);
        }

        // online softmax (rows gp, gp+8), quad reductions
        float mx0 = -1e30f, mx1 = -1e30f;
#pragma unroll
        for (int nt = 0; nt < 8; ++nt) {
            mx0 = fmaxf(mx0, fmaxf(sfr[nt][0], sfr[nt][1]));
            mx1 = fmaxf(mx1, fmaxf(sfr[nt][2], sfr[nt][3]));
        }
        mx0 = fmaxf(mx0, __shfl_xor_sync(0xffffffffu, mx0, 1));
        mx0 = fmaxf(mx0, __shfl_xor_sync(0xffffffffu, mx0, 2));
        mx1 = fmaxf(mx1, __shfl_xor_sync(0xffffffffu, mx1, 1));
        mx1 = fmaxf(mx1, __shfl_xor_sync(0xffffffffu, mx1, 2));
        float mn0 = fmaxf(m0, mx0), mn1 = fmaxf(m1, mx1);
        float a0 = __expf(m0 - mn0), a1 = __expf(m1 - mn1);
        m0 = mn0; m1 = mn1;

        float rs0 = 0.f, rs1 = 0.f;
#pragma unroll
        for (int nt = 0; nt < 8; ++nt) {
            sfr[nt][0] = __expf(sfr[nt][0] - mn0);
            sfr[nt][1] = __expf(sfr[nt][1] - mn0);
            sfr[nt][2] = __expf(sfr[nt][2] - mn1);
            sfr[nt][3] = __expf(sfr[nt][3] - mn1);
            rs0 += sfr[nt][0] + sfr[nt][1];
            rs1 += sfr[nt][2] + sfr[nt][3];
        }
        rs0 += __shfl_xor_sync(0xffffffffu, rs0, 1);
        rs0 += __shfl_xor_sync(0xffffffffu, rs0, 2);
        rs1 += __shfl_xor_sync(0xffffffffu, rs1, 1);
        rs1 += __shfl_xor_sync(0xffffffffu, rs1, 2);
        l0 = l0 * a0 + rs0;
        l1 = l1 * a1 + rs1;

        // pack P (C-frag -> A-frag register reuse, no smem)
        uint32_t pf[4][4];
#pragma unroll
        for (int ks2 = 0; ks2 < 4; ++ks2) {
            pf[ks2][0] = packh2(sfr[2 * ks2][0], sfr[2 * ks2][1]);
            pf[ks2][1] = packh2(sfr[2 * ks2][2], sfr[2 * ks2][3]);
            pf[ks2][2] = packh2(sfr[2 * ks2 + 1][0], sfr[2 * ks2 + 1][1]);
            pf[ks2][3] = packh2(sfr[2 * ks2 + 1][2], sfr[2 * ks2 + 1][3]);
        }

#pragma unroll
        for (int nt = 0; nt < 16; ++nt) {
            ofr[nt][0] *= a0; ofr[nt][1] *= a0;
            ofr[nt][2] *= a1; ofr[nt][3] *= a1;
        }

        // O += P @ V  (V via ldmatrix.trans)
#pragma unroll
        for (int nt2 = 0; nt2 < 8; ++nt2) {
#pragma unroll
            for (int ks2 = 0; ks2 < 4; ++ks2) {
                uint32_t ad = vb + (uint32_t)(((ks2 * 16 + (lane & 15)) * KSH +
                                               (2 * nt2 + (lane >> 4)) * 8) * 2);
                uint32_t r[4];
                ldsm4t(r, ad);
                mma_f16(ofr[2 * nt2], pf[ks2], r[0], r[1]);
                mma_f16(ofr[2 * nt2 + 1], pf[ks2], r[2], r[3]);
            }
        }
    }

    // finalize -> g_cath (fp16, GEMM2 A operand)
    float inv0 = 1.0f / l0, inv1 = 1.0f / l1;
    __half* o0 = g_cath + (size_t)(qb + w * 16 + gp) * K2 + h * HDIM;
    __half* o1 = o0 + (size_t)8 * K2;
#pragma unroll
    for (int nt = 0; nt < 16; ++nt) {
        int c = nt * 8 + 2 * qd;
        *(uint32_t*)(o0 + c) = packh2(ofr[nt][0] * inv0, ofr[nt][1] * inv0);
        *(uint32_t*)(o1 + c) = packh2(ofr[nt][2] * inv1, ofr[nt][3] * inv1);
    }
}

// ---------------------------------------------------------------------------
// gelu(mlp) -> g_cath fp16
// ---------------------------------------------------------------------------
__device__ __forceinline__ float gelu_t(float x) {
    return 0.5f * x * (1.0f + tanhf(0.7978845608028654f * (x + 0.044715f * x * x * x)));
}

__global__ void __launch_bounds__(256) gelu_cat() {
    int idx = blockIdx.x * 256 + threadIdx.x;
    const int per_row = MLPD / 4;
    if (idx >= LTOK * per_row) return;
    int row = idx / per_row;
    int c4 = idx - row * per_row;
    float4 v = *(const float4*)(g_h + (size_t)row * N1 + 3 * DMODEL + c4 * 4);
    uint2 u = make_uint2(packh2(gelu_t(v.x), gelu_t(v.y)),
                         packh2(gelu_t(v.z), gelu_t(v.w)));
    *(uint2*)(g_cath + (size_t)row * K2 + DMODEL + c4 * 4) = u;
}

// ---------------------------------------------------------------------------
// launch
// ---------------------------------------------------------------------------
extern "C" void kernel_launch(void* const* d_in, const int* in_sizes, int n_in,
                              void* d_out, int out_size) {
    const float* x   = (const float*)d_in[0];
    const float* vec = (const float*)d_in[1];
    const float* pe  = (const float*)d_in[2];
    const float* w1  = (const float*)d_in[3];
    const float* b1  = (const float*)d_in[4];
    const float* w2  = (const float*)d_in[5];
    const float* b2  = (const float*)d_in[6];
    const float* mw  = (const float*)d_in[7];
    const float* mb  = (const float*)d_in[8];
    const float* qsc = (const float*)d_in[9];
    const float* ksc = (const float*)d_in[10];
    float* out = (float*)d_out;

    __half *p_xmodh, *p_cath, *p_w1h, *p_w2h;
    float *p_h, *p_m;
    cudaGetSymbolAddress((void**)&p_xmodh, g_xmodh);
    cudaGetSymbolAddress((void**)&p_h, g_h);
    cudaGetSymbolAddress((void**)&p_cath, g_cath);
    cudaGetSymbolAddress((void**)&p_m, g_m);
    cudaGetSymbolAddress((void**)&p_w1h, g_w1h);
    cudaGetSymbolAddress((void**)&p_w2h, g_w2h);

    cudaFuncSetAttribute(flash_h, cudaFuncAttributeMaxDynamicSharedMemorySize, FL_SMEM);
    cudaFuncSetAttribute(mm_gemm<0>, cudaFuncAttributeMaxDynamicSharedMemorySize, GEMM_SMEM);
    cudaFuncSetAttribute(mm_gemm<1>, cudaFuncAttributeMaxDynamicSharedMemorySize, GEMM_SMEM);

    silu_k<<<(DMODEL + 255) / 256, 256>>>(vec);
    mod_gemv<<<(3 * DMODEL) / 8, 256>>>(mw, mb);
    ln_mod<<<LTOK, 256>>>(x);

    // fp16 weight conversion
    {
        int n4 = (N1 * DMODEL) / 4;
        cvt_h_k<<<(n4 + 255) / 256, 256>>>(w1, p_w1h, n4);
        n4 = (DMODEL * K2) / 4;
        cvt_h_k<<<(n4 + 255) / 256, 256>>>(w2, p_w2h, n4);
    }

    // h = x_mod @ w1^T + b1
    mm_gemm<0><<<dim3(LTOK / BM, N1 / BN), 256, GEMM_SMEM>>>(
        p_xmodh, p_w1h, p_h, N1, DMODEL, b1, nullptr, nullptr);

    qkv_prep<<<dim3(LTOK, NHEAD), 128>>>(pe, qsc, ksc);
    flash_h<<<dim3(LTOK / 128, NHEAD), 256, FL_SMEM>>>();
    gelu_cat<<<(LTOK * (MLPD / 4)) / 256, 256>>>();

    // out = x + gate * (cat @ w2^T + b2)
    mm_gemm<1><<<dim3(LTOK / BM, DMODEL / BN), 256, GEMM_SMEM>>>(
        p_cath, p_w2h, out, DMODEL, K2, b2, x, p_m + 2 * DMODEL);
}

// round 7
// speedup vs baseline: 7.9043x; 1.1294x over previous
#include <cuda_runtime.h>
#include <cuda_fp16.h>
#include <math.h>
#include <stdint.h>

// ---------------------------------------------------------------------------
// Problem constants (B = 1)
// ---------------------------------------------------------------------------
#define LTOK 4096
#define DMODEL 3072
#define NHEAD 24
#define HDIM 128
#define MLPD 12288
#define N1 (3 * DMODEL + MLPD)   // 21504
#define K2 (DMODEL + MLPD)       // 15360
#define QKVW (3 * DMODEL)        // 9216
#define EPSV 1e-6f
#define SM_SCALE 0.08838834764831843f

// ---------------------------------------------------------------------------
// Scratch
// ---------------------------------------------------------------------------
__device__ float  g_sv[DMODEL];
__device__ float  g_m[3 * DMODEL];
__device__ __half g_xmodh[(size_t)LTOK * DMODEL];
__device__ __half g_hh[(size_t)LTOK * QKVW];           // qkv part of GEMM1 out
__device__ __half g_qh[(size_t)NHEAD * LTOK * HDIM];   // pre-scaled by SM_SCALE
__device__ __half g_kh[(size_t)NHEAD * LTOK * HDIM];
__device__ __half g_vh[(size_t)NHEAD * LTOK * HDIM];
__device__ __half g_cath[(size_t)LTOK * K2];           // [attn | gelu(mlp)]
__device__ __half g_w1h[(size_t)N1 * DMODEL];
__device__ __half g_w2h[(size_t)DMODEL * K2];

// ---------------------------------------------------------------------------
// helpers (sm_75/80-era PTX only: cp.async, mma.sync, ldmatrix)
// ---------------------------------------------------------------------------
__device__ __forceinline__ uint32_t smem_u32(const void* p) {
    uint32_t a;
    asm("{ .reg .u64 t; cvta.to.shared.u64 t, %1; cvt.u32.u64 %0, t; }"
        : "=r"(a) : "l"(p));
    return a;
}
__device__ __forceinline__ void cp_async16(uint32_t s, const void* g) {
    asm volatile("cp.async.cg.shared.global [%0], [%1], 16;" :: "r"(s), "l"(g) : "memory");
}
__device__ __forceinline__ void mma_f16(float* c, const uint32_t* a,
                                        uint32_t b0, uint32_t b1) {
    asm volatile(
        "mma.sync.aligned.m16n8k16.row.col.f32.f16.f16.f32 "
        "{%0,%1,%2,%3}, {%4,%5,%6,%7}, {%8,%9}, {%0,%1,%2,%3};"
        : "+f"(c[0]), "+f"(c[1]), "+f"(c[2]), "+f"(c[3])
        : "r"(a[0]), "r"(a[1]), "r"(a[2]), "r"(a[3]), "r"(b0), "r"(b1));
}
__device__ __forceinline__ void ldsm4(uint32_t* r, uint32_t addr) {
    asm volatile("ldmatrix.sync.aligned.m8n8.x4.shared.b16 {%0,%1,%2,%3}, [%4];"
                 : "=r"(r[0]), "=r"(r[1]), "=r"(r[2]), "=r"(r[3]) : "r"(addr));
}
__device__ __forceinline__ void ldsm4t(uint32_t* r, uint32_t addr) {
    asm volatile("ldmatrix.sync.aligned.m8n8.x4.trans.shared.b16 {%0,%1,%2,%3}, [%4];"
                 : "=r"(r[0]), "=r"(r[1]), "=r"(r[2]), "=r"(r[3]) : "r"(addr));
}
__device__ __forceinline__ uint32_t packh2(float lo, float hi) {
    __half2 h = __floats2half2_rn(lo, hi);
    return *reinterpret_cast<uint32_t*>(&h);
}
__device__ __forceinline__ float gelu_t(float x) {
    return 0.5f * x * (1.0f + tanhf(0.7978845608028654f * (x + 0.044715f * x * x * x)));
}

// ---------------------------------------------------------------------------
// small kernels
// ---------------------------------------------------------------------------
__global__ void silu_k(const float* __restrict__ vec) {
    int i = blockIdx.x * blockDim.x + threadIdx.x;
    if (i < DMODEL) {
        float v = vec[i];
        g_sv[i] = v / (1.0f + expf(-v));
    }
}

__global__ void mod_gemv(const float* __restrict__ mw, const float* __restrict__ mb) {
    int j = blockIdx.x * 8 + (threadIdx.x >> 5);
    int lane = threadIdx.x & 31;
    const float* wr = mw + (size_t)j * DMODEL;
    float s = 0.f;
    for (int k = lane; k < DMODEL; k += 32) s += g_sv[k] * wr[k];
#pragma unroll
    for (int o = 16; o; o >>= 1) s += __shfl_down_sync(0xffffffffu, s, o);
    if (lane == 0) g_m[j] = s + mb[j];
}

__device__ __forceinline__ float block_sum256(float v, float* buf) {
#pragma unroll
    for (int o = 16; o; o >>= 1) v += __shfl_down_sync(0xffffffffu, v, o);
    int w = threadIdx.x >> 5;
    if ((threadIdx.x & 31) == 0) buf[w] = v;
    __syncthreads();
    float s = 0.f;
#pragma unroll
    for (int i = 0; i < 8; i++) s += buf[i];
    return s;
}

__global__ void __launch_bounds__(256) ln_mod(const float* __restrict__ x) {
    __shared__ float xs[DMODEL];
    __shared__ float rbuf[8];
    int row = blockIdx.x;
    const float* xr = x + (size_t)row * DMODEL;
    float s = 0.f;
    for (int i = threadIdx.x; i < DMODEL; i += 256) {
        float v = xr[i];
        xs[i] = v;
        s += v;
    }
    float mu = block_sum256(s, rbuf) * (1.0f / DMODEL);
    __syncthreads();
    float s2 = 0.f;
    for (int i = threadIdx.x; i < DMODEL; i += 256) {
        float d = xs[i] - mu;
        s2 += d * d;
    }
    float var = block_sum256(s2, rbuf) * (1.0f / DMODEL);
    float rstd = rsqrtf(var + EPSV);
    __half* xm = g_xmodh + (size_t)row * DMODEL;
    for (int i = threadIdx.x; i < DMODEL; i += 256) {
        float n = (xs[i] - mu) * rstd;
        xm[i] = __float2half_rn((1.0f + g_m[DMODEL + i]) * n + g_m[i]);
    }
}

// fp32 -> fp16 weight conversion
__global__ void __launch_bounds__(256) cvt_h_k(const float* __restrict__ src,
                                               __half* __restrict__ dst, int n4) {
    int i = blockIdx.x * 256 + threadIdx.x;
    if (i < n4) {
        float4 v = ((const float4*)src)[i];
        uint2 u = make_uint2(packh2(v.x, v.y), packh2(v.z, v.w));
        *(uint2*)(dst + (size_t)i * 4) = u;
    }
}

// ---------------------------------------------------------------------------
// fp16 mma.sync GEMM (NT), ldmatrix frags, single sync per K-chunk.
// EPI==0: GEMM1 -> qkv cols to g_hh (fp16), mlp cols gelu'd to g_cath (fp16)
// EPI==1: GEMM2 -> C = xres + gate * (acc + bias)   (fp32)
// ---------------------------------------------------------------------------
#define BM 128
#define BN 128
#define BK 32
#define NSTG 3
#define AROWH 40                          // 32 data halves + 8 pad
#define TILEH (BM * AROWH)
#define TILEB (TILEH * 2)
#define GEMM_SMEM (NSTG * 2 * TILEB)      // 61440 B

__device__ __forceinline__ void ld_stage(uint32_t As, uint32_t Bs,
                                         const __half* __restrict__ Ag,
                                         const __half* __restrict__ Bg,
                                         int K, int kb, int tid) {
#pragma unroll
    for (int it = 0; it < 2; ++it) {
        int id = it * 256 + tid;
        int row = id >> 2, c = id & 3;
        uint32_t off = (uint32_t)(row * AROWH * 2 + c * 16);
        const size_t goff = (size_t)row * K + kb + c * 8;
        cp_async16(As + off, Ag + goff);
        cp_async16(Bs + off, Bg + goff);
    }
}

template <int EPI>
__global__ void __launch_bounds__(256, 2)
mm_gemm(const __half* __restrict__ A, const __half* __restrict__ B,
        float* __restrict__ C, int Nt, int K,
        const float* __restrict__ bias,
        const float* __restrict__ xres, const float* __restrict__ gate) {
    extern __shared__ __half smh[];
    const uint32_t sA = smem_u32(smh);
    const uint32_t sB = sA + NSTG * TILEB;

    const int tid = threadIdx.x;
    const int wid = tid >> 5, lane = tid & 31;
    const int gp = lane >> 2, qd = lane & 3;
    const int warpM = (wid >> 2) * 64;
    const int warpN = (wid & 3) * 32;
    const int bm = blockIdx.x * BM;
    const int bn = blockIdx.y * BN;

    const __half* Ag = A + (size_t)bm * K;
    const __half* Bg = B + (size_t)bn * K;
    const int nch = K / BK;

    // ldmatrix lane base offsets (bytes, within a stage)
    const uint32_t aOff = (uint32_t)((warpM + (lane & 15)) * AROWH + (lane >> 4) * 8) * 2;
    const uint32_t bOff = (uint32_t)((warpN + (lane & 7)) * AROWH + (lane >> 3) * 8) * 2;

    float acc[4][4][4] = {};

    ld_stage(sA, sB, Ag, Bg, K, 0, tid);
    asm volatile("cp.async.commit_group;" ::: "memory");
    ld_stage(sA + TILEB, sB + TILEB, Ag, Bg, K, BK, tid);
    asm volatile("cp.async.commit_group;" ::: "memory");

    for (int j = 0; j < nch; ++j) {
        asm volatile("cp.async.wait_group 1;" ::: "memory");
        __syncthreads();
        const int c = j + 2;
        if (c < nch) {
            const int st = c % NSTG;
            ld_stage(sA + st * TILEB, sB + st * TILEB, Ag, Bg, K, c * BK, tid);
        }
        asm volatile("cp.async.commit_group;" ::: "memory");

        const uint32_t asb = sA + (j % NSTG) * TILEB + aOff;
        const uint32_t bsb = sB + (j % NSTG) * TILEB + bOff;

        // B frags: one ldsm4 per nt covers both k-halves
        uint32_t bf[4][4];
#pragma unroll
        for (int nt = 0; nt < 4; ++nt)
            ldsm4(bf[nt], bsb + (uint32_t)(nt * 8 * AROWH) * 2);

#pragma unroll
        for (int ks = 0; ks < 2; ++ks) {
            uint32_t af[4][4];
#pragma unroll
            for (int mt = 0; mt < 4; ++mt)
                ldsm4(af[mt], asb + (uint32_t)(mt * 16 * AROWH + ks * 16) * 2);
#pragma unroll
            for (int mt = 0; mt < 4; ++mt)
#pragma unroll
                for (int nt = 0; nt < 4; ++nt)
                    mma_f16(acc[mt][nt], af[mt], bf[nt][2 * ks], bf[nt][2 * ks + 1]);
        }
    }

    // epilogue
    if (EPI == 0) {
        const bool is_qkv = (bn < QKVW);
#pragma unroll
        for (int nt = 0; nt < 4; ++nt) {
            const int col = bn + warpN + nt * 8 + 2 * qd;
            const float b0 = bias[col], b1v = bias[col + 1];
#pragma unroll
            for (int mt = 0; mt < 4; ++mt) {
                const int r0 = bm + warpM + mt * 16 + gp;
#pragma unroll
                for (int half = 0; half < 2; ++half) {
                    const int row = r0 + half * 8;
                    float v0 = acc[mt][nt][half * 2 + 0] + b0;
                    float v1 = acc[mt][nt][half * 2 + 1] + b1v;
                    if (is_qkv) {
                        *(uint32_t*)(g_hh + (size_t)row * QKVW + col) = packh2(v0, v1);
                    } else {
                        // mlp col in h-space [3D, N1) -> cat col = col - 2D in [D, K2)
                        *(uint32_t*)(g_cath + (size_t)row * K2 + (col - 2 * DMODEL)) =
                            packh2(gelu_t(v0), gelu_t(v1));
                    }
                }
            }
        }
    } else {
#pragma unroll
        for (int nt = 0; nt < 4; ++nt) {
            const int col = bn + warpN + nt * 8 + 2 * qd;
            const float b0 = bias[col], b1v = bias[col + 1];
            const float g0 = gate[col], g1 = gate[col + 1];
#pragma unroll
            for (int mt = 0; mt < 4; ++mt) {
                const int r0 = bm + warpM + mt * 16 + gp;
#pragma unroll
                for (int half = 0; half < 2; ++half) {
                    const int row = r0 + half * 8;
                    const size_t off = (size_t)row * Nt + col;
                    float2 xr = *(const float2*)(xres + off);
                    float v0 = xr.x + g0 * (acc[mt][nt][half * 2 + 0] + b0);
                    float v1 = xr.y + g1 * (acc[mt][nt][half * 2 + 1] + b1v);
                    *(float2*)(C + off) = make_float2(v0, v1);
                }
            }
        }
    }
}

// ---------------------------------------------------------------------------
// QKV prep: RMSNorm + RoPE + head-major fp16 relayout (q pre-scaled)
// ---------------------------------------------------------------------------
__global__ void __launch_bounds__(128)
qkv_prep(const float* __restrict__ pe,
         const float* __restrict__ q_scale, const float* __restrict__ k_scale) {
    int i = blockIdx.x;
    int hh = blockIdx.y;
    int d = threadIdx.x;

    const __half* hp = g_hh + (size_t)i * QKVW + hh * HDIM;
    float qv = __half2float(hp[d]);
    float kv = __half2float(hp[DMODEL + d]);
    float vv = __half2float(hp[2 * DMODEL + d]);

    __shared__ float rb[2][4];
    float sq = qv * qv, sk = kv * kv;
#pragma unroll
    for (int o = 16; o; o >>= 1) {
        sq += __shfl_down_sync(0xffffffffu, sq, o);
        sk += __shfl_down_sync(0xffffffffu, sk, o);
    }
    if ((d & 31) == 0) { rb[0][d >> 5] = sq; rb[1][d >> 5] = sk; }
    __syncthreads();
    float ssq = rb[0][0] + rb[0][1] + rb[0][2] + rb[0][3];
    float ssk = rb[1][0] + rb[1][1] + rb[1][2] + rb[1][3];
    float rq = rsqrtf(ssq * (1.0f / HDIM) + EPSV);
    float rk = rsqrtf(ssk * (1.0f / HDIM) + EPSV);

    float qn = qv * rq * q_scale[d];
    float kn = kv * rk * k_scale[d];

    int e = d >> 1;
    int base = (i * (HDIM / 2) + e) * 4 + (d & 1) * 2;
    float p0 = pe[base], p1 = pe[base + 1];
    float qp = __shfl_xor_sync(0xffffffffu, qn, 1);
    float kp = __shfl_xor_sync(0xffffffffu, kn, 1);
    float qe = (d & 1) ? qp : qn, qo = (d & 1) ? qn : qp;
    float ke = (d & 1) ? kp : kn, ko = (d & 1) ? kn : kp;
    float qr = p0 * qe + p1 * qo;
    float kr = p0 * ke + p1 * ko;

    size_t o = ((size_t)hh * LTOK + i) * HDIM + d;
    g_qh[o] = __float2half_rn(qr * SM_SCALE);
    g_kh[o] = __float2half_rn(kr);
    g_vh[o] = __float2half_rn(vv);
}

// ---------------------------------------------------------------------------
// Flash attention fp16 mma (unchanged from R5 — validated)
// ---------------------------------------------------------------------------
#define KSH 136
#define KVBUF (64 * KSH * 2)
#define FL_SMEM (4 * KVBUF)

__device__ __forceinline__ void load_kv(uint32_t kd, uint32_t vd,
                                        const __half* __restrict__ Kg,
                                        const __half* __restrict__ Vg,
                                        int kt, int tid) {
#pragma unroll
    for (int it = 0; it < 4; ++it) {
        int id = it * 256 + tid;
        int row = id >> 4, c = id & 15;
        uint32_t off = (uint32_t)(row * KSH * 2 + c * 16);
        const size_t goff = (size_t)(kt + row) * HDIM + c * 8;
        cp_async16(kd + off, Kg + goff);
        cp_async16(vd + off, Vg + goff);
    }
}

__global__ void __launch_bounds__(256, 1) flash_h() {
    extern __shared__ __half smh[];
    const uint32_t kbase0 = smem_u32(smh);
    const uint32_t vbase0 = kbase0 + 2 * KVBUF;

    const int h = blockIdx.y;
    const int qb = blockIdx.x * 128;
    const int tid = threadIdx.x;
    const int w = tid >> 5, lane = tid & 31;
    const int gp = lane >> 2, qd = lane & 3;

    const __half* Kg = g_kh + (size_t)h * LTOK * HDIM;
    const __half* Vg = g_vh + (size_t)h * LTOK * HDIM;

    uint32_t qf[8][4];
    {
        const __half* q0 = g_qh + ((size_t)h * LTOK + qb + w * 16 + gp) * HDIM;
        const __half* q1 = q0 + 8 * HDIM;
#pragma unroll
        for (int ks = 0; ks < 8; ++ks) {
            int c = ks * 16 + 2 * qd;
            qf[ks][0] = *(const uint32_t*)(q0 + c);
            qf[ks][1] = *(const uint32_t*)(q1 + c);
            qf[ks][2] = *(const uint32_t*)(q0 + c + 8);
            qf[ks][3] = *(const uint32_t*)(q1 + c + 8);
        }
    }

    float ofr[16][4] = {};
    float m0 = -1e30f, m1 = -1e30f, l0 = 0.f, l1 = 0.f;

    load_kv(kbase0, vbase0, Kg, Vg, 0, tid);
    asm volatile("cp.async.commit_group;" ::: "memory");

    const int nT = LTOK / 64;
    for (int t = 0; t < nT; ++t) {
        const int buf = t & 1;
        asm volatile("cp.async.wait_group 0;" ::: "memory");
        __syncthreads();
        if (t + 1 < nT)
            load_kv(kbase0 + (buf ^ 1) * KVBUF, vbase0 + (buf ^ 1) * KVBUF,
                    Kg, Vg, (t + 1) * 64, tid);
        asm volatile("cp.async.commit_group;" ::: "memory");

        const uint32_t kb = kbase0 + buf * KVBUF;
        const uint32_t vb = vbase0 + buf * KVBUF;

        float sfr[8][4] = {};
#pragma unroll
        for (int nt = 0; nt < 8; ++nt) {
            uint32_t bb[8][2];
#pragma unroll
            for (int j = 0; j < 4; ++j) {
                uint32_t ad = kb + (uint32_t)(((nt * 8 + (lane & 7)) * KSH +
                                               j * 32 + (lane >> 3) * 8) * 2);
                uint32_t r[4];
                ldsm4(r, ad);
                bb[2 * j][0] = r[0]; bb[2 * j][1] = r[1];
                bb[2 * j + 1][0] = r[2]; bb[2 * j + 1][1] = r[3];
            }
#pragma unroll
            for (int ks = 0; ks < 8; ++ks)
                mma_f16(sfr[nt], qf[ks], bb[ks][0], bb[ks][1]);
        }

        float mx0 = -1e30f, mx1 = -1e30f;
#pragma unroll
        for (int nt = 0; nt < 8; ++nt) {
            mx0 = fmaxf(mx0, fmaxf(sfr[nt][0], sfr[nt][1]));
            mx1 = fmaxf(mx1, fmaxf(sfr[nt][2], sfr[nt][3]));
        }
        mx0 = fmaxf(mx0, __shfl_xor_sync(0xffffffffu, mx0, 1));
        mx0 = fmaxf(mx0, __shfl_xor_sync(0xffffffffu, mx0, 2));
        mx1 = fmaxf(mx1, __shfl_xor_sync(0xffffffffu, mx1, 1));
        mx1 = fmaxf(mx1, __shfl_xor_sync(0xffffffffu, mx1, 2));
        float mn0 = fmaxf(m0, mx0), mn1 = fmaxf(m1, mx1);
        float a0 = __expf(m0 - mn0), a1 = __expf(m1 - mn1);
        m0 = mn0; m1 = mn1;

        float rs0 = 0.f, rs1 = 0.f;
#pragma unroll
        for (int nt = 0; nt < 8; ++nt) {
            sfr[nt][0] = __expf(sfr[nt][0] - mn0);
            sfr[nt][1] = __expf(sfr[nt][1] - mn0);
            sfr[nt][2] = __expf(sfr[nt][2] - mn1);
            sfr[nt][3] = __expf(sfr[nt][3] - mn1);
            rs0 += sfr[nt][0] + sfr[nt][1];
            rs1 += sfr[nt][2] + sfr[nt][3];
        }
        rs0 += __shfl_xor_sync(0xffffffffu, rs0, 1);
        rs0 += __shfl_xor_sync(0xffffffffu, rs0, 2);
        rs1 += __shfl_xor_sync(0xffffffffu, rs1, 1);
        rs1 += __shfl_xor_sync(0xffffffffu, rs1, 2);
        l0 = l0 * a0 + rs0;
        l1 = l1 * a1 + rs1;

        uint32_t pf[4][4];
#pragma unroll
        for (int ks2 = 0; ks2 < 4; ++ks2) {
            pf[ks2][0] = packh2(sfr[2 * ks2][0], sfr[2 * ks2][1]);
            pf[ks2][1] = packh2(sfr[2 * ks2][2], sfr[2 * ks2][3]);
            pf[ks2][2] = packh2(sfr[2 * ks2 + 1][0], sfr[2 * ks2 + 1][1]);
            pf[ks2][3] = packh2(sfr[2 * ks2 + 1][2], sfr[2 * ks2 + 1][3]);
        }

#pragma unroll
        for (int nt = 0; nt < 16; ++nt) {
            ofr[nt][0] *= a0; ofr[nt][1] *= a0;
            ofr[nt][2] *= a1; ofr[nt][3] *= a1;
        }

#pragma unroll
        for (int nt2 = 0; nt2 < 8; ++nt2) {
#pragma unroll
            for (int ks2 = 0; ks2 < 4; ++ks2) {
                uint32_t ad = vb + (uint32_t)(((ks2 * 16 + (lane & 15)) * KSH +
                                               (2 * nt2 + (lane >> 4)) * 8) * 2);
                uint32_t r[4];
                ldsm4t(r, ad);
                mma_f16(ofr[2 * nt2], pf[ks2], r[0], r[1]);
                mma_f16(ofr[2 * nt2 + 1], pf[ks2], r[2], r[3]);
            }
        }
    }

    float inv0 = 1.0f / l0, inv1 = 1.0f / l1;
    __half* o0 = g_cath + (size_t)(qb + w * 16 + gp) * K2 + h * HDIM;
    __half* o1 = o0 + (size_t)8 * K2;
#pragma unroll
    for (int nt = 0; nt < 16; ++nt) {
        int c = nt * 8 + 2 * qd;
        *(uint32_t*)(o0 + c) = packh2(ofr[nt][0] * inv0, ofr[nt][1] * inv0);
        *(uint32_t*)(o1 + c) = packh2(ofr[nt][2] * inv1, ofr[nt][3] * inv1);
    }
}

// ---------------------------------------------------------------------------
// launch
// ---------------------------------------------------------------------------
extern "C" void kernel_launch(void* const* d_in, const int* in_sizes, int n_in,
                              void* d_out, int out_size) {
    const float* x   = (const float*)d_in[0];
    const float* vec = (const float*)d_in[1];
    const float* pe  = (const float*)d_in[2];
    const float* w1  = (const float*)d_in[3];
    const float* b1  = (const float*)d_in[4];
    const float* w2  = (const float*)d_in[5];
    const float* b2  = (const float*)d_in[6];
    const float* mw  = (const float*)d_in[7];
    const float* mb  = (const float*)d_in[8];
    const float* qsc = (const float*)d_in[9];
    const float* ksc = (const float*)d_in[10];
    float* out = (float*)d_out;

    __half *p_xmodh, *p_cath, *p_w1h, *p_w2h;
    float *p_m;
    cudaGetSymbolAddress((void**)&p_xmodh, g_xmodh);
    cudaGetSymbolAddress((void**)&p_cath, g_cath);
    cudaGetSymbolAddress((void**)&p_m, g_m);
    cudaGetSymbolAddress((void**)&p_w1h, g_w1h);
    cudaGetSymbolAddress((void**)&p_w2h, g_w2h);

    cudaFuncSetAttribute(flash_h, cudaFuncAttributeMaxDynamicSharedMemorySize, FL_SMEM);
    cudaFuncSetAttribute(mm_gemm<0>, cudaFuncAttributeMaxDynamicSharedMemorySize, GEMM_SMEM);
    cudaFuncSetAttribute(mm_gemm<1>, cudaFuncAttributeMaxDynamicSharedMemorySize, GEMM_SMEM);

    silu_k<<<(DMODEL + 255) / 256, 256>>>(vec);
    mod_gemv<<<(3 * DMODEL) / 8, 256>>>(mw, mb);
    ln_mod<<<LTOK, 256>>>(x);

    // fp16 weight conversion
    {
        int n4 = (N1 * DMODEL) / 4;
        cvt_h_k<<<(n4 + 255) / 256, 256>>>(w1, p_w1h, n4);
        n4 = (DMODEL * K2) / 4;
        cvt_h_k<<<(n4 + 255) / 256, 256>>>(w2, p_w2h, n4);
    }

    // GEMM1: qkv -> g_hh (fp16), mlp -> gelu -> g_cath (fp16)
    mm_gemm<0><<<dim3(LTOK / BM, N1 / BN), 256, GEMM_SMEM>>>(
        p_xmodh, p_w1h, nullptr, N1, DMODEL, b1, nullptr, nullptr);

    qkv_prep<<<dim3(LTOK, NHEAD), 128>>>(pe, qsc, ksc);
    flash_h<<<dim3(LTOK / 128, NHEAD), 256, FL_SMEM>>>();

    // GEMM2: out = x + gate * (cat @ w2^T + b2)
    mm_gemm<1><<<dim3(LTOK / BM, DMODEL / BN), 256, GEMM_SMEM>>>(
        p_cath, p_w2h, out, DMODEL, K2, b2, x, p_m + 2 * DMODEL);
}